// round 1
// baseline (speedup 1.0000x reference)
#include <cuda_runtime.h>

#define Nn 50000
#define Ee 1600000
#define FIN 256
#define Hh 2
#define Dd 64
#define HD 128
#define NEG 0.2f
#define EPSf 1e-9f

// ---------------- scratch (static device globals; no runtime alloc) ----------
__device__ float g_h[3][Nn * HD];    // [2] = h_src raw; [0]/[1] ping-pong hop buffers
__device__ float g_hdst[Nn * HD];    // residual branch
__device__ float g_hs[4][Nn * HD];   // [0..2] = transformed hops, [3] = h0
__device__ float g_asrc[Nn * Hh];
__device__ float g_adst[Nn * Hh];
__device__ float g_logit[Ee * Hh];
__device__ float g_exd[Ee * Hh];
__device__ float g_exs[Ee * Hh];
__device__ float g_aedge[Ee * Hh];
__device__ float g_maxd[Nn * Hh];
__device__ float g_maxs[Nn * Hh];
__device__ float g_sumd[Nn * Hh];
__device__ float g_sums[Nn * Hh];

// ---------------- helpers ---------------------------------------------------
__device__ __forceinline__ void atomicMaxFloat(float* addr, float val) {
    if (val >= 0.f) atomicMax((int*)addr, __float_as_int(val));
    else            atomicMin((unsigned int*)addr, (unsigned int)__float_as_int(val));
}

__device__ __forceinline__ void red_add_v4(float* addr, float4 v) {
    asm volatile("red.global.add.v4.f32 [%0], {%1,%2,%3,%4};"
                 :: "l"(addr), "f"(v.x), "f"(v.y), "f"(v.z), "f"(v.w)
                 : "memory");
}

__device__ __forceinline__ float leaky(float x) { return x > 0.f ? x : NEG * x; }

// ---------------- GEMM: h_src = feat@W_src ; h_dst = feat@W_dst + b ----------
__global__ __launch_bounds__(256) void gemm_h_kernel(
    const float* __restrict__ A, const float* __restrict__ Wsrc,
    const float* __restrict__ Wdst, const float* __restrict__ bias)
{
    const int BM = 128, BK = 8, TM = 8, TN = 8;
    __shared__ float As[BK][BM];
    __shared__ float Bs[BK][128];
    const float* W = blockIdx.y ? Wdst : Wsrc;
    float* Out = blockIdx.y ? g_hdst : g_h[2];
    int row0 = blockIdx.x * BM;
    int tid = threadIdx.x;
    int tx = tid & 15, ty = tid >> 4;
    float acc[TM][TN] = {};
    for (int k0 = 0; k0 < FIN; k0 += BK) {
        #pragma unroll
        for (int i = tid; i < BM * BK; i += 256) {
            int r = i >> 3, kk = i & 7;
            int gr = row0 + r;
            As[kk][r] = (gr < Nn) ? A[gr * FIN + k0 + kk] : 0.f;
        }
        #pragma unroll
        for (int i = tid; i < BK * 128; i += 256) {
            int kk = i >> 7, c = i & 127;
            Bs[kk][c] = W[(k0 + kk) * HD + c];
        }
        __syncthreads();
        #pragma unroll
        for (int kk = 0; kk < BK; kk++) {
            float a[TM], b[TN];
            #pragma unroll
            for (int i = 0; i < TM; i++) a[i] = As[kk][ty * TM + i];
            #pragma unroll
            for (int j = 0; j < TN; j++) b[j] = Bs[kk][tx * TN + j];
            #pragma unroll
            for (int i = 0; i < TM; i++)
                #pragma unroll
                for (int j = 0; j < TN; j++) acc[i][j] += a[i] * b[j];
        }
        __syncthreads();
    }
    #pragma unroll
    for (int i = 0; i < TM; i++) {
        int r = row0 + ty * TM + i;
        if (r >= Nn) continue;
        #pragma unroll
        for (int j = 0; j < TN; j++) {
            int c = tx * TN + j;
            float v = acc[i][j];
            if (blockIdx.y) v += bias[c];
            Out[r * HD + c] = v;
        }
    }
}

// ---------------- attention projections: a_src/a_dst [N,H] -------------------
__global__ void attn_gemm_kernel(const float* __restrict__ A,
                                 const float* __restrict__ Wsrc,
                                 const float* __restrict__ Wdst)
{
    int gw = (blockIdx.x * blockDim.x + threadIdx.x) >> 5;
    int lane = threadIdx.x & 31;
    if (gw >= Nn * 4) return;
    int n = gw >> 2;
    int q = gw & 3;          // 0,1: a_src h ; 2,3: a_dst h
    int hh = q & 1;
    const float* W = (q < 2) ? Wsrc : Wdst;
    float s = 0.f;
    #pragma unroll
    for (int j = 0; j < FIN / 32; j++) {
        int k = lane + 32 * j;
        s += A[n * FIN + k] * W[k * Hh + hh];
    }
    #pragma unroll
    for (int o = 16; o; o >>= 1) s += __shfl_xor_sync(0xffffffffu, s, o);
    if (lane == 0) {
        if (q < 2) g_asrc[n * Hh + hh] = s;
        else       g_adst[n * Hh + hh] = s;
    }
}

// ---------------- softmax accumulator init ----------------------------------
__global__ void init_softmax_kernel() {
    int i = blockIdx.x * blockDim.x + threadIdx.x;
    if (i < Nn * Hh) {
        float ninf = __int_as_float(0xff800000);
        g_maxd[i] = ninf; g_maxs[i] = ninf;
        g_sumd[i] = 0.f;  g_sums[i] = 0.f;
    }
}

// ---------------- edge logits + segment max ---------------------------------
__global__ void edge_logit_kernel(const int* __restrict__ src, const int* __restrict__ dst) {
    int e = blockIdx.x * blockDim.x + threadIdx.x;
    if (e >= Ee) return;
    int s = src[e], d = dst[e];
    float2 as = *(const float2*)&g_asrc[s * 2];
    float2 ad = *(const float2*)&g_adst[d * 2];
    float l0 = leaky(as.x + ad.x);
    float l1 = leaky(as.y + ad.y);
    *(float2*)&g_logit[e * 2] = make_float2(l0, l1);
    atomicMaxFloat(&g_maxd[d * 2], l0);
    atomicMaxFloat(&g_maxd[d * 2 + 1], l1);
    atomicMaxFloat(&g_maxs[s * 2], l0);
    atomicMaxFloat(&g_maxs[s * 2 + 1], l1);
}

// ---------------- exp + segment sums ----------------------------------------
__global__ void edge_exp_kernel(const int* __restrict__ src, const int* __restrict__ dst) {
    int e = blockIdx.x * blockDim.x + threadIdx.x;
    if (e >= Ee) return;
    int s = src[e], d = dst[e];
    float2 l  = *(const float2*)&g_logit[e * 2];
    float2 md = *(const float2*)&g_maxd[d * 2];
    float2 ms = *(const float2*)&g_maxs[s * 2];
    float ed0 = __expf(l.x - md.x), ed1 = __expf(l.y - md.y);
    float es0 = __expf(l.x - ms.x), es1 = __expf(l.y - ms.y);
    *(float2*)&g_exd[e * 2] = make_float2(ed0, ed1);
    *(float2*)&g_exs[e * 2] = make_float2(es0, es1);
    atomicAdd(&g_sumd[d * 2], ed0);     atomicAdd(&g_sumd[d * 2 + 1], ed1);
    atomicAdd(&g_sums[s * 2], es0);     atomicAdd(&g_sums[s * 2 + 1], es1);
}

// ---------------- final symmetric edge weights ------------------------------
__global__ void edge_a_kernel(const int* __restrict__ src, const int* __restrict__ dst) {
    int e = blockIdx.x * blockDim.x + threadIdx.x;
    if (e >= Ee) return;
    int s = src[e], d = dst[e];
    float2 ed = *(const float2*)&g_exd[e * 2];
    float2 es = *(const float2*)&g_exs[e * 2];
    float2 sd = *(const float2*)&g_sumd[d * 2];
    float2 ss = *(const float2*)&g_sums[s * 2];
    float a0 = sqrtf(fmaxf(ed.x / sd.x, EPSf) * fmaxf(es.x / ss.x, EPSf));
    float a1 = sqrtf(fmaxf(ed.y / sd.y, EPSf) * fmaxf(es.y / ss.y, EPSf));
    *(float2*)&g_aedge[e * 2] = make_float2(a0, a1);
}

// ---------------- zero a hop buffer -----------------------------------------
__global__ void zero_h_kernel(int sel) {
    int i = blockIdx.x * blockDim.x + threadIdx.x;
    if (i < Nn * HD / 4) ((float4*)g_h[sel])[i] = make_float4(0.f, 0.f, 0.f, 0.f);
}

// ---------------- diffusion scatter: h_next[dst] += a * h_cur[src] ----------
__global__ __launch_bounds__(256) void scatter_kernel(
    const int* __restrict__ src, const int* __restrict__ dst,
    int in_sel, int out_sel)
{
    int t = blockIdx.x * blockDim.x + threadIdx.x;   // E*32 threads, 4 floats each
    int e = t >> 5;
    if (e >= Ee) return;
    int i = t & 31;                   // chunk within the 128-float row
    int hh = i >> 4;
    int s = src[e], d = dst[e];
    const float* in = g_h[in_sel];
    float* out = g_h[out_sel];
    float a = g_aedge[e * 2 + hh];
    float4 v = *(const float4*)&in[s * HD + i * 4];
    v.x *= a; v.y *= a; v.z *= a; v.w *= a;
    red_add_v4(&out[d * HD + i * 4], v);
}

// ---------------- feat_trans: per-(n,h) layernorm-ish + pos emb --------------
__global__ void feat_trans_kernel(const float* __restrict__ scale,
                                  const float* __restrict__ offset,
                                  const float* __restrict__ pemb,
                                  int in_sel, int k, int out_sel)
{
    int gw = (blockIdx.x * blockDim.x + threadIdx.x) >> 5;
    int lane = threadIdx.x & 31;
    if (gw >= Nn * Hh) return;
    int n = gw >> 1, hh = gw & 1;
    const float* in = g_h[in_sel];
    float* out = g_hs[out_sel];
    int b = n * HD + hh * Dd;
    float x0 = in[b + lane];
    float x1 = in[b + lane + 32];
    float s = x0 + x1, sq = x0 * x0 + x1 * x1;
    #pragma unroll
    for (int o = 16; o; o >>= 1) {
        s  += __shfl_xor_sync(0xffffffffu, s,  o);
        sq += __shfl_xor_sync(0xffffffffu, sq, o);
    }
    float mean = s * (1.f / Dd);
    float var = sq * (1.f / Dd) - mean * mean + EPSf;
    float rs = rsqrtf(var);
    int pb = k * Hh * Dd + hh * Dd;
    float y0 = (x0 - mean) * scale[pb + lane]      * rs + offset[pb + lane]      + pemb[pb + lane];
    float y1 = (x1 - mean) * scale[pb + lane + 32] * rs + offset[pb + lane + 32] + pemb[pb + lane + 32];
    out[b + lane]      = y0;
    out[b + lane + 32] = y1;
}

// ---------------- hop attention + residual output ----------------------------
__global__ void final_kernel(const float* __restrict__ attn_l,
                             const float* __restrict__ attn_r,
                             float* __restrict__ out)
{
    int gw = (blockIdx.x * blockDim.x + threadIdx.x) >> 5;
    int lane = threadIdx.x & 31;
    if (gw >= Nn * Hh) return;
    int n = gw >> 1, hh = gw & 1;
    int b = n * HD + hh * Dd;
    int ab = hh * Dd;

    float h0a = g_hs[3][b + lane], h0b = g_hs[3][b + lane + 32];
    float s0a = g_hs[0][b + lane], s0b = g_hs[0][b + lane + 32];
    float s1a = g_hs[1][b + lane], s1b = g_hs[1][b + lane + 32];
    float s2a = g_hs[2][b + lane], s2b = g_hs[2][b + lane + 32];
    float la = attn_l[ab + lane], lb = attn_l[ab + lane + 32];
    float ra = attn_r[ab + lane], rb = attn_r[ab + lane + 32];

    float al = h0a * la + h0b * lb;
    float w0 = s0a * ra + s0b * rb;
    float w1 = s1a * ra + s1b * rb;
    float w2 = s2a * ra + s2b * rb;
    #pragma unroll
    for (int o = 16; o; o >>= 1) {
        al += __shfl_xor_sync(0xffffffffu, al, o);
        w0 += __shfl_xor_sync(0xffffffffu, w0, o);
        w1 += __shfl_xor_sync(0xffffffffu, w1, o);
        w2 += __shfl_xor_sync(0xffffffffu, w2, o);
    }
    float l0 = leaky(w0 + al), l1 = leaky(w1 + al), l2 = leaky(w2 + al);
    float m = fmaxf(l0, fmaxf(l1, l2));
    float e0 = __expf(l0 - m), e1 = __expf(l1 - m), e2 = __expf(l2 - m);
    float inv = 1.f / (e0 + e1 + e2);
    e0 *= inv; e1 *= inv; e2 *= inv;

    out[b + lane]      = s0a * e0 + s1a * e1 + s2a * e2 + g_hdst[b + lane];
    out[b + lane + 32] = s0b * e0 + s1b * e1 + s2b * e2 + g_hdst[b + lane + 32];
}

// ---------------- launch ------------------------------------------------------
extern "C" void kernel_launch(void* const* d_in, const int* in_sizes, int n_in,
                              void* d_out, int out_size)
{
    const float* feat  = (const float*)d_in[0];
    const int*   src   = (const int*)d_in[1];
    const int*   dst   = (const int*)d_in[2];
    const float* Wsrc  = (const float*)d_in[3];
    const float* Wdst  = (const float*)d_in[4];
    const float* bdst  = (const float*)d_in[5];
    const float* Wasrc = (const float*)d_in[6];
    const float* Wadst = (const float*)d_in[7];
    const float* scale = (const float*)d_in[8];
    const float* offs  = (const float*)d_in[9];
    const float* pemb  = (const float*)d_in[10];
    const float* hal   = (const float*)d_in[11];
    const float* har   = (const float*)d_in[12];
    float* out = (float*)d_out;

    // projections
    gemm_h_kernel<<<dim3((Nn + 127) / 128, 2), 256>>>(feat, Wsrc, Wdst, bdst);
    attn_gemm_kernel<<<(Nn * 4 * 32 + 255) / 256, 256>>>(feat, Wasrc, Wadst);

    // symmetric edge softmax
    init_softmax_kernel<<<(Nn * Hh + 255) / 256, 256>>>();
    edge_logit_kernel<<<(Ee + 255) / 256, 256>>>(src, dst);
    edge_exp_kernel<<<(Ee + 255) / 256, 256>>>(src, dst);
    edge_a_kernel<<<(Ee + 255) / 256, 256>>>(src, dst);

    const int FT_GRID = (Nn * Hh * 32 + 255) / 256;
    const int SC_GRID = (Ee * 32 + 255) / 256;
    const int ZR_GRID = (Nn * HD / 4 + 255) / 256;

    // h0 = feat_trans(h_src, 0)
    feat_trans_kernel<<<FT_GRID, 256>>>(scale, offs, pemb, 2, 0, 3);

    // hop 1: h_src (g_h[2]) -> g_h[0]
    zero_h_kernel<<<ZR_GRID, 256>>>(0);
    scatter_kernel<<<SC_GRID, 256>>>(src, dst, 2, 0);
    feat_trans_kernel<<<FT_GRID, 256>>>(scale, offs, pemb, 0, 1, 0);

    // hop 2: g_h[0] -> g_h[1]
    zero_h_kernel<<<ZR_GRID, 256>>>(1);
    scatter_kernel<<<SC_GRID, 256>>>(src, dst, 0, 1);
    feat_trans_kernel<<<FT_GRID, 256>>>(scale, offs, pemb, 1, 2, 1);

    // hop 3: g_h[1] -> g_h[0]
    zero_h_kernel<<<ZR_GRID, 256>>>(0);
    scatter_kernel<<<SC_GRID, 256>>>(src, dst, 1, 0);
    feat_trans_kernel<<<FT_GRID, 256>>>(scale, offs, pemb, 0, 3, 2);

    // hop attention + residual
    final_kernel<<<FT_GRID, 256>>>(hal, har, out);
}

// round 2
// speedup vs baseline: 1.6534x; 1.6534x over previous
#include <cuda_runtime.h>

#define Nn 50000
#define Ee 1600000
#define FIN 256
#define HD 128
#define NEG 0.2f
#define EPSf 1e-9f

// ---------------- scratch (static device globals) ----------------------------
__device__ float g_hsrc[Nn * HD];
__device__ float g_hdst[Nn * HD];
__device__ float g_hbuf[2][Nn * HD];   // hop raw ping-pong
__device__ float g_hs[3][Nn * HD];     // [0]=hs1t, [1]=hs2t, [2]=h0t
__device__ float g_asrc[Nn * 2];
__device__ float g_adst[Nn * 2];
__device__ float g_ex[Ee * 2];
__device__ float g_acsr[Ee * 2];       // edge weights in CSR order
__device__ int   g_pos[Ee];            // orig edge -> CSR slot
__device__ int   g_srcc[Ee];           // src index in CSR order
__device__ int   g_cnt[Nn];
__device__ int   g_rp[Nn + 1];
__device__ int   g_cur[Nn];
__device__ float g_sumd[Nn * 2];
__device__ float g_sums[Nn * 2];

__device__ __forceinline__ float leaky(float x) { return x > 0.f ? x : NEG * x; }

// ---------------- GEMM: h_src = feat@W_src ; h_dst = feat@W_dst + b ----------
__global__ __launch_bounds__(256) void gemm_h_kernel(
    const float* __restrict__ A, const float* __restrict__ Wsrc,
    const float* __restrict__ Wdst, const float* __restrict__ bias)
{
    const int BM = 128, BK = 16;
    __shared__ float As[BK][BM];
    __shared__ float Bs[BK][BM];
    const float* W = blockIdx.y ? Wdst : Wsrc;
    float* Out = blockIdx.y ? g_hdst : g_hsrc;
    int row0 = blockIdx.x * BM;
    int tid = threadIdx.x;
    int tx = tid & 15, ty = tid >> 4;

    // load indices
    int ar = tid & 127, ah = tid >> 7;          // A: row, k-half (0/1 -> 8 k's)
    int bk = tid >> 4, bc = (tid & 15) * 8;     // B: k-row, col group of 8

    float acc[8][8] = {};
    for (int k0 = 0; k0 < FIN; k0 += BK) {
        int gr = row0 + ar;
        float4 a0, a1;
        if (gr < Nn) {
            const float4* ap = (const float4*)&A[gr * FIN + k0 + ah * 8];
            a0 = ap[0]; a1 = ap[1];
        } else {
            a0 = make_float4(0.f, 0.f, 0.f, 0.f); a1 = a0;
        }
        As[ah * 8 + 0][ar] = a0.x; As[ah * 8 + 1][ar] = a0.y;
        As[ah * 8 + 2][ar] = a0.z; As[ah * 8 + 3][ar] = a0.w;
        As[ah * 8 + 4][ar] = a1.x; As[ah * 8 + 5][ar] = a1.y;
        As[ah * 8 + 6][ar] = a1.z; As[ah * 8 + 7][ar] = a1.w;

        const float4* bp = (const float4*)&W[(k0 + bk) * HD + bc];
        float4 b0 = bp[0], b1 = bp[1];
        *(float4*)&Bs[bk][bc] = b0;
        *(float4*)&Bs[bk][bc + 4] = b1;
        __syncthreads();
        #pragma unroll
        for (int kk = 0; kk < BK; kk++) {
            float a[8], b[8];
            #pragma unroll
            for (int i = 0; i < 8; i++) a[i] = As[kk][ty * 8 + i];
            #pragma unroll
            for (int j = 0; j < 8; j++) b[j] = Bs[kk][tx * 8 + j];
            #pragma unroll
            for (int i = 0; i < 8; i++)
                #pragma unroll
                for (int j = 0; j < 8; j++) acc[i][j] += a[i] * b[j];
        }
        __syncthreads();
    }
    #pragma unroll
    for (int i = 0; i < 8; i++) {
        int r = row0 + ty * 8 + i;
        if (r >= Nn) continue;
        #pragma unroll
        for (int j = 0; j < 8; j++) {
            float v = acc[i][j];
            if (blockIdx.y) v += bias[tx * 8 + j];
            Out[r * HD + tx * 8 + j] = v;
        }
    }
}

// ---------------- attention projections: a_src/a_dst [N,2] -------------------
__global__ void attn_gemm_kernel(const float* __restrict__ A,
                                 const float* __restrict__ Wsrc,
                                 const float* __restrict__ Wdst)
{
    int gw = (blockIdx.x * blockDim.x + threadIdx.x) >> 5;
    int lane = threadIdx.x & 31;
    if (gw >= Nn * 4) return;
    int n = gw >> 2;
    int q = gw & 3;
    int hh = q & 1;
    const float* W = (q < 2) ? Wsrc : Wdst;
    float s = 0.f;
    #pragma unroll
    for (int j = 0; j < FIN / 32; j++) {
        int k = lane + 32 * j;
        s += A[n * FIN + k] * W[k * 2 + hh];
    }
    #pragma unroll
    for (int o = 16; o; o >>= 1) s += __shfl_xor_sync(0xffffffffu, s, o);
    if (lane == 0) {
        if (q < 2) g_asrc[n * 2 + hh] = s;
        else       g_adst[n * 2 + hh] = s;
    }
}

// ---------------- init: zero counters + softmax sums -------------------------
__global__ void init_kernel() {
    int i = blockIdx.x * blockDim.x + threadIdx.x;
    if (i < Nn) {
        g_cnt[i] = 0;
        ((float2*)g_sumd)[i] = make_float2(0.f, 0.f);
        ((float2*)g_sums)[i] = make_float2(0.f, 0.f);
    }
}

// ---------------- CSR build --------------------------------------------------
__global__ void hist_kernel(const int* __restrict__ dst) {
    int e = blockIdx.x * blockDim.x + threadIdx.x;
    if (e < Ee) atomicAdd(&g_cnt[dst[e]], 1);
}

__global__ __launch_bounds__(1024) void scan_kernel() {
    __shared__ int part[1024];
    const int CH = (Nn + 1023) / 1024;
    int t = threadIdx.x;
    int start = t * CH;
    int s = 0;
    for (int i = 0; i < CH; i++) {
        int idx = start + i;
        if (idx < Nn) s += g_cnt[idx];
    }
    part[t] = s;
    __syncthreads();
    for (int off = 1; off < 1024; off <<= 1) {
        int v = (t >= off) ? part[t - off] : 0;
        __syncthreads();
        part[t] += v;
        __syncthreads();
    }
    int base = (t == 0) ? 0 : part[t - 1];
    for (int i = 0; i < CH; i++) {
        int idx = start + i;
        if (idx < Nn) {
            g_rp[idx] = base;
            g_cur[idx] = base;
            base += g_cnt[idx];
        }
    }
    if (t == 1023) g_rp[Nn] = Ee;
}

__global__ void place_kernel(const int* __restrict__ src, const int* __restrict__ dst) {
    int e = blockIdx.x * blockDim.x + threadIdx.x;
    if (e >= Ee) return;
    int d = dst[e];
    int pos = atomicAdd(&g_cur[d], 1);
    g_pos[e] = pos;
    g_srcc[pos] = src[e];
}

// ---------------- edge pass A: logit -> exp -> segment sums ------------------
// (softmax is shift-invariant; logits are bounded so skip the max pass)
__global__ void edgeA_kernel(const int* __restrict__ src, const int* __restrict__ dst) {
    int e = blockIdx.x * blockDim.x + threadIdx.x;
    if (e >= Ee) return;
    int s = src[e], d = dst[e];
    float2 as = ((const float2*)g_asrc)[s];
    float2 ad = ((const float2*)g_adst)[d];
    float e0 = __expf(leaky(as.x + ad.x));
    float e1 = __expf(leaky(as.y + ad.y));
    ((float2*)g_ex)[e] = make_float2(e0, e1);
    atomicAdd(&g_sumd[d * 2], e0);     atomicAdd(&g_sumd[d * 2 + 1], e1);
    atomicAdd(&g_sums[s * 2], e0);     atomicAdd(&g_sums[s * 2 + 1], e1);
}

// ---------------- edge pass B: symmetric weights, scatter into CSR order -----
__global__ void edgeB_kernel(const int* __restrict__ src, const int* __restrict__ dst) {
    int e = blockIdx.x * blockDim.x + threadIdx.x;
    if (e >= Ee) return;
    int s = src[e], d = dst[e];
    float2 ex = ((const float2*)g_ex)[e];
    float2 sd = ((const float2*)g_sumd)[d];
    float2 ss = ((const float2*)g_sums)[s];
    float a0 = sqrtf(fmaxf(ex.x / sd.x, EPSf) * fmaxf(ex.x / ss.x, EPSf));
    float a1 = sqrtf(fmaxf(ex.y / sd.y, EPSf) * fmaxf(ex.y / ss.y, EPSf));
    ((float2*)g_acsr)[g_pos[e]] = make_float2(a0, a1);
}

// ---------------- shared feat_trans epilogue helper --------------------------
// acc = this lane's 4 consecutive floats of the 128-row (lane*4 .. lane*4+3).
// Normalization groups are 16-lane halves (one per head).
__device__ __forceinline__ float4 feat_trans4(
    float4 acc, int lane, int k,
    const float* __restrict__ scale, const float* __restrict__ offset,
    const float* __restrict__ pemb)
{
    float s = acc.x + acc.y + acc.z + acc.w;
    float sq = acc.x * acc.x + acc.y * acc.y + acc.z * acc.z + acc.w * acc.w;
    #pragma unroll
    for (int o = 8; o; o >>= 1) {
        s  += __shfl_xor_sync(0xffffffffu, s,  o, 16);
        sq += __shfl_xor_sync(0xffffffffu, sq, o, 16);
    }
    float mean = s * (1.f / 64.f);
    float var = sq * (1.f / 64.f) - mean * mean + EPSf;
    float rs = rsqrtf(var);
    float4 sc = ((const float4*)scale)[k * 32 + lane];
    float4 of = ((const float4*)offset)[k * 32 + lane];
    float4 pe = ((const float4*)pemb)[k * 32 + lane];
    float4 y;
    y.x = (acc.x - mean) * sc.x * rs + of.x + pe.x;
    y.y = (acc.y - mean) * sc.y * rs + of.y + pe.y;
    y.z = (acc.z - mean) * sc.z * rs + of.z + pe.z;
    y.w = (acc.w - mean) * sc.w * rs + of.w + pe.w;
    return y;
}

// ---------------- feat_trans of h_src (k=0) -> h0t ---------------------------
__global__ void ft0_kernel(const float* __restrict__ scale,
                           const float* __restrict__ offset,
                           const float* __restrict__ pemb)
{
    int gw = (blockIdx.x * blockDim.x + threadIdx.x) >> 5;
    int lane = threadIdx.x & 31;
    if (gw >= Nn) return;
    float4 x = ((const float4*)g_hsrc)[gw * 32 + lane];
    ((float4*)g_hs[2])[gw * 32 + lane] = feat_trans4(x, lane, 0, scale, offset, pemb);
}

// ---------------- diffusion hop (gather) + fused feat_trans ------------------
// in_sel: 0=g_hsrc 1=g_hbuf[0] 2=g_hbuf[1]
__global__ __launch_bounds__(256) void hop_kernel(
    int in_sel, int raw_sel, int ts_sel, int k,
    const float* __restrict__ scale, const float* __restrict__ offset,
    const float* __restrict__ pemb)
{
    int gw = (blockIdx.x * blockDim.x + threadIdx.x) >> 5;
    int lane = threadIdx.x & 31;
    if (gw >= Nn) return;
    const float4* in4 = (const float4*)(in_sel == 0 ? g_hsrc : g_hbuf[in_sel - 1]);
    int hh = lane >> 4;
    int b = g_rp[gw], e = g_rp[gw + 1];
    float4 acc = make_float4(0.f, 0.f, 0.f, 0.f);
    #pragma unroll 2
    for (int pos = b; pos < e; pos++) {
        int s = g_srcc[pos];
        float a = g_acsr[pos * 2 + hh];
        float4 v = in4[s * 32 + lane];
        acc.x += a * v.x; acc.y += a * v.y; acc.z += a * v.z; acc.w += a * v.w;
    }
    ((float4*)g_hbuf[raw_sel])[gw * 32 + lane] = acc;
    ((float4*)g_hs[ts_sel])[gw * 32 + lane] =
        feat_trans4(acc, lane, k, scale, offset, pemb);
}

// ---------------- hop 3 + feat_trans + hop attention + residual --------------
__global__ __launch_bounds__(256) void hop3_final_kernel(
    const float* __restrict__ scale, const float* __restrict__ offset,
    const float* __restrict__ pemb,
    const float* __restrict__ attn_l, const float* __restrict__ attn_r,
    float* __restrict__ out)
{
    int gw = (blockIdx.x * blockDim.x + threadIdx.x) >> 5;
    int lane = threadIdx.x & 31;
    if (gw >= Nn) return;
    const float4* in4 = (const float4*)g_hbuf[1];
    int hh = lane >> 4;
    int b = g_rp[gw], e = g_rp[gw + 1];
    float4 acc = make_float4(0.f, 0.f, 0.f, 0.f);
    #pragma unroll 2
    for (int pos = b; pos < e; pos++) {
        int s = g_srcc[pos];
        float a = g_acsr[pos * 2 + hh];
        float4 v = in4[s * 32 + lane];
        acc.x += a * v.x; acc.y += a * v.y; acc.z += a * v.z; acc.w += a * v.w;
    }
    float4 s2 = feat_trans4(acc, lane, 3, scale, offset, pemb);

    float4 s0 = ((const float4*)g_hs[0])[gw * 32 + lane];
    float4 s1 = ((const float4*)g_hs[1])[gw * 32 + lane];
    float4 h0 = ((const float4*)g_hs[2])[gw * 32 + lane];
    float4 al4 = ((const float4*)attn_l)[lane];
    float4 ar4 = ((const float4*)attn_r)[lane];

    float al = h0.x * al4.x + h0.y * al4.y + h0.z * al4.z + h0.w * al4.w;
    float w0 = s0.x * ar4.x + s0.y * ar4.y + s0.z * ar4.z + s0.w * ar4.w;
    float w1 = s1.x * ar4.x + s1.y * ar4.y + s1.z * ar4.z + s1.w * ar4.w;
    float w2 = s2.x * ar4.x + s2.y * ar4.y + s2.z * ar4.z + s2.w * ar4.w;
    #pragma unroll
    for (int o = 8; o; o >>= 1) {
        al += __shfl_xor_sync(0xffffffffu, al, o, 16);
        w0 += __shfl_xor_sync(0xffffffffu, w0, o, 16);
        w1 += __shfl_xor_sync(0xffffffffu, w1, o, 16);
        w2 += __shfl_xor_sync(0xffffffffu, w2, o, 16);
    }
    float l0 = leaky(w0 + al), l1 = leaky(w1 + al), l2 = leaky(w2 + al);
    float m = fmaxf(l0, fmaxf(l1, l2));
    float e0 = __expf(l0 - m), e1 = __expf(l1 - m), e2 = __expf(l2 - m);
    float inv = 1.f / (e0 + e1 + e2);
    e0 *= inv; e1 *= inv; e2 *= inv;

    float4 hd = ((const float4*)g_hdst)[gw * 32 + lane];
    float4 o4;
    o4.x = s0.x * e0 + s1.x * e1 + s2.x * e2 + hd.x;
    o4.y = s0.y * e0 + s1.y * e1 + s2.y * e2 + hd.y;
    o4.z = s0.z * e0 + s1.z * e1 + s2.z * e2 + hd.z;
    o4.w = s0.w * e0 + s1.w * e1 + s2.w * e2 + hd.w;
    ((float4*)out)[gw * 32 + lane] = o4;
}

// ---------------- launch ------------------------------------------------------
extern "C" void kernel_launch(void* const* d_in, const int* in_sizes, int n_in,
                              void* d_out, int out_size)
{
    const float* feat  = (const float*)d_in[0];
    const int*   src   = (const int*)d_in[1];
    const int*   dst   = (const int*)d_in[2];
    const float* Wsrc  = (const float*)d_in[3];
    const float* Wdst  = (const float*)d_in[4];
    const float* bdst  = (const float*)d_in[5];
    const float* Wasrc = (const float*)d_in[6];
    const float* Wadst = (const float*)d_in[7];
    const float* scale = (const float*)d_in[8];
    const float* offs  = (const float*)d_in[9];
    const float* pemb  = (const float*)d_in[10];
    const float* hal   = (const float*)d_in[11];
    const float* har   = (const float*)d_in[12];
    float* out = (float*)d_out;

    const int EG = (Ee + 255) / 256;           // 6250
    const int NWG = (Nn * 32 + 255) / 256;     // 6250

    // projections
    gemm_h_kernel<<<dim3((Nn + 127) / 128, 2), 256>>>(feat, Wsrc, Wdst, bdst);
    attn_gemm_kernel<<<(Nn * 4 * 32 + 255) / 256, 256>>>(feat, Wasrc, Wadst);

    // CSR build + softmax accumulators
    init_kernel<<<(Nn + 255) / 256, 256>>>();
    hist_kernel<<<EG, 256>>>(dst);
    scan_kernel<<<1, 1024>>>();
    place_kernel<<<EG, 256>>>(src, dst);

    // symmetric edge softmax (2 passes, no max)
    edgeA_kernel<<<EG, 256>>>(src, dst);
    edgeB_kernel<<<EG, 256>>>(src, dst);

    // h0 = feat_trans(h_src, 0)
    ft0_kernel<<<NWG, 256>>>(scale, offs, pemb);

    // diffusion hops (gather, fused feat_trans)
    hop_kernel<<<NWG, 256>>>(0, 0, 0, 1, scale, offs, pemb);  // hsrc -> buf0, hs0
    hop_kernel<<<NWG, 256>>>(1, 1, 1, 2, scale, offs, pemb);  // buf0 -> buf1, hs1
    hop3_final_kernel<<<NWG, 256>>>(scale, offs, pemb, hal, har, out);
}

// round 8
// speedup vs baseline: 1.7393x; 1.0520x over previous
#include <cuda_runtime.h>
#include <cuda_fp16.h>

#define Nn 50000
#define Ee 1600000
#define FIN 256
#define HD 128
#define NEG 0.2f
#define EPSf 1e-9f

// ---------------- scratch (static device globals) ----------------------------
__device__ float  g_hsrc[Nn * HD];        // fp32 h_src (for ft0 precision)
__device__ float  g_hdst[Nn * HD];        // residual branch
__device__ __half g_h16[3][Nn * HD];      // fp16 gather sources: [0]=h_src,[1],[2]=hops
__device__ float  g_hs[3][Nn * HD];       // [0]=hs1t, [1]=hs2t, [2]=h0t
__device__ float  g_asrc[Nn * 2];
__device__ float  g_adst[Nn * 2];
__device__ float  g_acsr[Ee * 2];         // CSR order: exp(logit) then final weight
__device__ int    g_srcc[Ee];             // src index in CSR order
__device__ int    g_cnt[Nn];
__device__ int    g_rp[Nn + 1];
__device__ int    g_cur[Nn];
__device__ float  g_sumd[Nn * 2];
__device__ float  g_sums[Nn * 2];

__device__ __forceinline__ float leaky(float x) { return x > 0.f ? x : NEG * x; }

// ---------------- GEMM: h_src = feat@W_src ; h_dst = feat@W_dst + b ----------
__global__ __launch_bounds__(256) void gemm_h_kernel(
    const float* __restrict__ A, const float* __restrict__ Wsrc,
    const float* __restrict__ Wdst, const float* __restrict__ bias)
{
    const int BM = 128, BK = 16;
    __shared__ float As[BK][BM];
    __shared__ float Bs[BK][BM];
    const float* W = blockIdx.y ? Wdst : Wsrc;
    float* Out = blockIdx.y ? g_hdst : g_hsrc;
    int row0 = blockIdx.x * BM;
    int tid = threadIdx.x;
    int tx = tid & 15, ty = tid >> 4;
    int ar = tid & 127, ah = tid >> 7;
    int bk = tid >> 4, bc = (tid & 15) * 8;

    float acc[8][8] = {};
    for (int k0 = 0; k0 < FIN; k0 += BK) {
        int gr = row0 + ar;
        float4 a0, a1;
        if (gr < Nn) {
            const float4* ap = (const float4*)&A[gr * FIN + k0 + ah * 8];
            a0 = ap[0]; a1 = ap[1];
        } else {
            a0 = make_float4(0.f, 0.f, 0.f, 0.f); a1 = a0;
        }
        As[ah * 8 + 0][ar] = a0.x; As[ah * 8 + 1][ar] = a0.y;
        As[ah * 8 + 2][ar] = a0.z; As[ah * 8 + 3][ar] = a0.w;
        As[ah * 8 + 4][ar] = a1.x; As[ah * 8 + 5][ar] = a1.y;
        As[ah * 8 + 6][ar] = a1.z; As[ah * 8 + 7][ar] = a1.w;

        const float4* bp = (const float4*)&W[(k0 + bk) * HD + bc];
        float4 b0 = bp[0], b1 = bp[1];
        *(float4*)&Bs[bk][bc] = b0;
        *(float4*)&Bs[bk][bc + 4] = b1;
        __syncthreads();
        #pragma unroll
        for (int kk = 0; kk < BK; kk++) {
            float a[8], b[8];
            #pragma unroll
            for (int i = 0; i < 8; i++) a[i] = As[kk][ty * 8 + i];
            #pragma unroll
            for (int j = 0; j < 8; j++) b[j] = Bs[kk][tx * 8 + j];
            #pragma unroll
            for (int i = 0; i < 8; i++)
                #pragma unroll
                for (int j = 0; j < 8; j++) acc[i][j] += a[i] * b[j];
        }
        __syncthreads();
    }
    #pragma unroll
    for (int i = 0; i < 8; i++) {
        int r = row0 + ty * 8 + i;
        if (r >= Nn) continue;
        #pragma unroll
        for (int j = 0; j < 8; j++) {
            float v = acc[i][j];
            if (blockIdx.y) v += bias[tx * 8 + j];
            Out[r * HD + tx * 8 + j] = v;
        }
    }
}

// ---------------- attention projections: a_src/a_dst [N,2] -------------------
__global__ void attn_gemm_kernel(const float* __restrict__ A,
                                 const float* __restrict__ Wsrc,
                                 const float* __restrict__ Wdst)
{
    int gw = (blockIdx.x * blockDim.x + threadIdx.x) >> 5;
    int lane = threadIdx.x & 31;
    if (gw >= Nn * 4) return;
    int n = gw >> 2;
    int q = gw & 3;
    int hh = q & 1;
    const float* W = (q < 2) ? Wsrc : Wdst;
    float s = 0.f;
    #pragma unroll
    for (int j = 0; j < FIN / 32; j++) {
        int k = lane + 32 * j;
        s += A[n * FIN + k] * W[k * 2 + hh];
    }
    #pragma unroll
    for (int o = 16; o; o >>= 1) s += __shfl_xor_sync(0xffffffffu, s, o);
    if (lane == 0) {
        if (q < 2) g_asrc[n * 2 + hh] = s;
        else       g_adst[n * 2 + hh] = s;
    }
}

// ---------------- init: zero counters + softmax sums -------------------------
__global__ void init_kernel() {
    int i = blockIdx.x * blockDim.x + threadIdx.x;
    if (i < Nn) {
        g_cnt[i] = 0;
        ((float2*)g_sumd)[i] = make_float2(0.f, 0.f);
        ((float2*)g_sums)[i] = make_float2(0.f, 0.f);
    }
}

// ---------------- CSR build --------------------------------------------------
__global__ void hist_kernel(const int* __restrict__ dst) {
    int e = blockIdx.x * blockDim.x + threadIdx.x;
    if (e < Ee) atomicAdd(&g_cnt[dst[e]], 1);
}

__global__ __launch_bounds__(1024) void scan_kernel() {
    __shared__ int part[1024];
    const int CH = (Nn + 1023) / 1024;
    int t = threadIdx.x;
    int start = t * CH;
    int s = 0;
    for (int i = 0; i < CH; i++) {
        int idx = start + i;
        if (idx < Nn) s += g_cnt[idx];
    }
    part[t] = s;
    __syncthreads();
    for (int off = 1; off < 1024; off <<= 1) {
        int v = (t >= off) ? part[t - off] : 0;
        __syncthreads();
        part[t] += v;
        __syncthreads();
    }
    int base = (t == 0) ? 0 : part[t - 1];
    for (int i = 0; i < CH; i++) {
        int idx = start + i;
        if (idx < Nn) {
            g_rp[idx] = base;
            g_cur[idx] = base;
            base += g_cnt[idx];
        }
    }
    if (t == 1023) g_rp[Nn] = Ee;
}

// ---------------- place + edge logits/exp + segment sums (fused) -------------
__global__ void place_edge_kernel(const int* __restrict__ src, const int* __restrict__ dst) {
    int e = blockIdx.x * blockDim.x + threadIdx.x;
    if (e >= Ee) return;
    int s = src[e], d = dst[e];
    int pos = atomicAdd(&g_cur[d], 1);
    g_srcc[pos] = s;
    float2 as = ((const float2*)g_asrc)[s];
    float2 ad = ((const float2*)g_adst)[d];
    float e0 = __expf(leaky(as.x + ad.x));
    float e1 = __expf(leaky(as.y + ad.y));
    ((float2*)g_acsr)[pos] = make_float2(e0, e1);
    atomicAdd(&g_sumd[d * 2], e0);     atomicAdd(&g_sumd[d * 2 + 1], e1);
    atomicAdd(&g_sums[s * 2], e0);     atomicAdd(&g_sums[s * 2 + 1], e1);
}

// ---------------- final symmetric weights, node-parallel over CSR ------------
__global__ void edgeB_kernel() {
    int gw = (blockIdx.x * blockDim.x + threadIdx.x) >> 5;
    int lane = threadIdx.x & 31;
    if (gw >= Nn) return;
    int b = g_rp[gw], e = g_rp[gw + 1];
    if (b == e) return;
    float2 sd = ((const float2*)g_sumd)[gw];
    float rd0 = 1.f / sd.x, rd1 = 1.f / sd.y;
    for (int pos = b + lane; pos < e; pos += 32) {
        int s = g_srcc[pos];
        float2 ex = ((const float2*)g_acsr)[pos];
        float2 ss = ((const float2*)g_sums)[s];
        float a0 = sqrtf(fmaxf(ex.x * rd0, EPSf) * fmaxf(ex.x / ss.x, EPSf));
        float a1 = sqrtf(fmaxf(ex.y * rd1, EPSf) * fmaxf(ex.y / ss.y, EPSf));
        ((float2*)g_acsr)[pos] = make_float2(a0, a1);
    }
}

// ---------------- shared feat_trans epilogue helper --------------------------
__device__ __forceinline__ float4 feat_trans4(
    float4 acc, int lane, int k,
    const float* __restrict__ scale, const float* __restrict__ offset,
    const float* __restrict__ pemb)
{
    float s = acc.x + acc.y + acc.z + acc.w;
    float sq = acc.x * acc.x + acc.y * acc.y + acc.z * acc.z + acc.w * acc.w;
    #pragma unroll
    for (int o = 8; o; o >>= 1) {
        s  += __shfl_xor_sync(0xffffffffu, s,  o, 16);
        sq += __shfl_xor_sync(0xffffffffu, sq, o, 16);
    }
    float mean = s * (1.f / 64.f);
    float var = sq * (1.f / 64.f) - mean * mean + EPSf;
    float rs = rsqrtf(var);
    float4 sc = ((const float4*)scale)[k * 32 + lane];
    float4 of = ((const float4*)offset)[k * 32 + lane];
    float4 pe = ((const float4*)pemb)[k * 32 + lane];
    float4 y;
    y.x = (acc.x - mean) * sc.x * rs + of.x + pe.x;
    y.y = (acc.y - mean) * sc.y * rs + of.y + pe.y;
    y.z = (acc.z - mean) * sc.z * rs + of.z + pe.z;
    y.w = (acc.w - mean) * sc.w * rs + of.w + pe.w;
    return y;
}

__device__ __forceinline__ void store_half4(__half* __restrict__ out16,
                                            int idx4, float4 v)
{
    uint2 raw;
    *(__half2*)&raw.x = __floats2half2_rn(v.x, v.y);
    *(__half2*)&raw.y = __floats2half2_rn(v.z, v.w);
    ((uint2*)out16)[idx4] = raw;
}

// ---------------- ft0: feat_trans(h_src,0) -> h0t, plus fp16 copy of h_src ---
__global__ void ft0_kernel(const float* __restrict__ scale,
                           const float* __restrict__ offset,
                           const float* __restrict__ pemb)
{
    int gw = (blockIdx.x * blockDim.x + threadIdx.x) >> 5;
    int lane = threadIdx.x & 31;
    if (gw >= Nn) return;
    float4 x = ((const float4*)g_hsrc)[gw * 32 + lane];
    store_half4(g_h16[0], gw * 32 + lane, x);
    ((float4*)g_hs[2])[gw * 32 + lane] = feat_trans4(x, lane, 0, scale, offset, pemb);
}

// ---------------- fp16 gather core: acc = sum a * h16[src] -------------------
__device__ __forceinline__ float4 gather_row(const __half* __restrict__ in16,
                                             int b, int e, int lane, int hh)
{
    const uint2* in = (const uint2*)in16;
    float4 acc = make_float4(0.f, 0.f, 0.f, 0.f);
    #pragma unroll 2
    for (int pos = b; pos < e; pos++) {
        int s = g_srcc[pos];
        float a = g_acsr[pos * 2 + hh];
        uint2 raw = in[s * 32 + lane];
        float2 lo = __half22float2(*(const __half2*)&raw.x);
        float2 hi = __half22float2(*(const __half2*)&raw.y);
        acc.x += a * lo.x; acc.y += a * lo.y;
        acc.z += a * hi.x; acc.w += a * hi.y;
    }
    return acc;
}

// ---------------- diffusion hop (gather) + fused feat_trans ------------------
// Buffer selection via integer selectors resolved in DEVICE code only.
__global__ __launch_bounds__(256) void hop_kernel(
    int in_sel, int out_sel, int ts_sel, int k,
    const float* __restrict__ scale, const float* __restrict__ offset,
    const float* __restrict__ pemb)
{
    int gw = (blockIdx.x * blockDim.x + threadIdx.x) >> 5;
    int lane = threadIdx.x & 31;
    if (gw >= Nn) return;
    const __half* in16 = g_h16[in_sel];
    __half* out16 = g_h16[out_sel];
    int hh = lane >> 4;
    int b = g_rp[gw], e = g_rp[gw + 1];
    float4 acc = gather_row(in16, b, e, lane, hh);
    store_half4(out16, gw * 32 + lane, acc);
    ((float4*)g_hs[ts_sel])[gw * 32 + lane] =
        feat_trans4(acc, lane, k, scale, offset, pemb);
}

// ---------------- hop 3 + feat_trans + hop attention + residual --------------
__global__ __launch_bounds__(256) void hop3_final_kernel(
    const float* __restrict__ scale, const float* __restrict__ offset,
    const float* __restrict__ pemb,
    const float* __restrict__ attn_l, const float* __restrict__ attn_r,
    float* __restrict__ out)
{
    int gw = (blockIdx.x * blockDim.x + threadIdx.x) >> 5;
    int lane = threadIdx.x & 31;
    if (gw >= Nn) return;
    const __half* in16 = g_h16[2];
    int hh = lane >> 4;
    int b = g_rp[gw], e = g_rp[gw + 1];
    float4 acc = gather_row(in16, b, e, lane, hh);
    float4 s2 = feat_trans4(acc, lane, 3, scale, offset, pemb);

    float4 s0 = ((const float4*)g_hs[0])[gw * 32 + lane];
    float4 s1 = ((const float4*)g_hs[1])[gw * 32 + lane];
    float4 h0 = ((const float4*)g_hs[2])[gw * 32 + lane];
    float4 al4 = ((const float4*)attn_l)[lane];
    float4 ar4 = ((const float4*)attn_r)[lane];

    float al = h0.x * al4.x + h0.y * al4.y + h0.z * al4.z + h0.w * al4.w;
    float w0 = s0.x * ar4.x + s0.y * ar4.y + s0.z * ar4.z + s0.w * ar4.w;
    float w1 = s1.x * ar4.x + s1.y * ar4.y + s1.z * ar4.z + s1.w * ar4.w;
    float w2 = s2.x * ar4.x + s2.y * ar4.y + s2.z * ar4.z + s2.w * ar4.w;
    #pragma unroll
    for (int o = 8; o; o >>= 1) {
        al += __shfl_xor_sync(0xffffffffu, al, o, 16);
        w0 += __shfl_xor_sync(0xffffffffu, w0, o, 16);
        w1 += __shfl_xor_sync(0xffffffffu, w1, o, 16);
        w2 += __shfl_xor_sync(0xffffffffu, w2, o, 16);
    }
    float l0 = leaky(w0 + al), l1 = leaky(w1 + al), l2 = leaky(w2 + al);
    float m = fmaxf(l0, fmaxf(l1, l2));
    float e0 = __expf(l0 - m), e1 = __expf(l1 - m), e2 = __expf(l2 - m);
    float inv = 1.f / (e0 + e1 + e2);
    e0 *= inv; e1 *= inv; e2 *= inv;

    float4 hd = ((const float4*)g_hdst)[gw * 32 + lane];
    float4 o4;
    o4.x = s0.x * e0 + s1.x * e1 + s2.x * e2 + hd.x;
    o4.y = s0.y * e0 + s1.y * e1 + s2.y * e2 + hd.y;
    o4.z = s0.z * e0 + s1.z * e1 + s2.z * e2 + hd.z;
    o4.w = s0.w * e0 + s1.w * e1 + s2.w * e2 + hd.w;
    ((float4*)out)[gw * 32 + lane] = o4;
}

// ---------------- launch ------------------------------------------------------
extern "C" void kernel_launch(void* const* d_in, const int* in_sizes, int n_in,
                              void* d_out, int out_size)
{
    const float* feat  = (const float*)d_in[0];
    const int*   src   = (const int*)d_in[1];
    const int*   dst   = (const int*)d_in[2];
    const float* Wsrc  = (const float*)d_in[3];
    const float* Wdst  = (const float*)d_in[4];
    const float* bdst  = (const float*)d_in[5];
    const float* Wasrc = (const float*)d_in[6];
    const float* Wadst = (const float*)d_in[7];
    const float* scale = (const float*)d_in[8];
    const float* offs  = (const float*)d_in[9];
    const float* pemb  = (const float*)d_in[10];
    const float* hal   = (const float*)d_in[11];
    const float* har   = (const float*)d_in[12];
    float* out = (float*)d_out;

    const int EG = (Ee + 255) / 256;
    const int NWG = (Nn * 32 + 255) / 256;

    // projections
    gemm_h_kernel<<<dim3((Nn + 127) / 128, 2), 256>>>(feat, Wsrc, Wdst, bdst);
    attn_gemm_kernel<<<(Nn * 4 * 32 + 255) / 256, 256>>>(feat, Wasrc, Wadst);

    // CSR build + fused edge logits/exp/sums
    init_kernel<<<(Nn + 255) / 256, 256>>>();
    hist_kernel<<<EG, 256>>>(dst);
    scan_kernel<<<1, 1024>>>();
    place_edge_kernel<<<EG, 256>>>(src, dst);
    edgeB_kernel<<<NWG, 256>>>();

    // h0 = feat_trans(h_src, 0) + fp16 copy of h_src
    ft0_kernel<<<NWG, 256>>>(scale, offs, pemb);

    // diffusion hops (fp16 gather, fp32 accumulate, fused feat_trans)
    hop_kernel<<<NWG, 256>>>(0, 1, 0, 1, scale, offs, pemb);
    hop_kernel<<<NWG, 256>>>(1, 2, 1, 2, scale, offs, pemb);
    hop3_final_kernel<<<NWG, 256>>>(scale, offs, pemb, hal, har, out);
}

// round 9
// speedup vs baseline: 1.7455x; 1.0036x over previous
#include <cuda_runtime.h>
#include <cuda_fp16.h>

#define Nn 50000
#define Ee 1600000
#define FIN 256
#define HD 128
#define NEG 0.2f
#define EPSf 1e-9f

// ---------------- scratch (static device globals) ----------------------------
__device__ float  g_hsrc[Nn * HD];        // fp32 h_src (for ft0 precision)
__device__ float  g_hdst[Nn * HD];        // residual branch
__device__ __half g_h16[3][Nn * HD];      // fp16 gather sources: [0]=h_src,[1],[2]=hops
__device__ float  g_hs[3][Nn * HD];       // [0]=hs1t, [1]=hs2t, [2]=h0t
__device__ float  g_asrc[Nn * 2];
__device__ float  g_adst[Nn * 2];
__device__ float  g_acsr[Ee * 2];         // CSR order: exp(logit) then final weight
__device__ int    g_srcc[Ee];             // src index in CSR order
__device__ int    g_cnt[Nn];
__device__ int    g_rp[Nn + 1];
__device__ int    g_cur[Nn];
__device__ float  g_sumd[Nn * 2];
__device__ float  g_sums[Nn * 2];

__device__ __forceinline__ float leaky(float x) { return x > 0.f ? x : NEG * x; }

// ---------------- GEMM: h_src = feat@W_src ; h_dst = feat@W_dst + b ----------
__global__ __launch_bounds__(256) void gemm_h_kernel(
    const float* __restrict__ A, const float* __restrict__ Wsrc,
    const float* __restrict__ Wdst, const float* __restrict__ bias)
{
    const int BM = 128, BK = 16;
    __shared__ float As[BK][BM];
    __shared__ float Bs[BK][BM];
    const float* W = blockIdx.y ? Wdst : Wsrc;
    float* Out = blockIdx.y ? g_hdst : g_hsrc;
    int row0 = blockIdx.x * BM;
    int tid = threadIdx.x;
    int tx = tid & 15, ty = tid >> 4;
    int ar = tid & 127, ah = tid >> 7;
    int bk = tid >> 4, bc = (tid & 15) * 8;

    float acc[8][8] = {};
    for (int k0 = 0; k0 < FIN; k0 += BK) {
        int gr = row0 + ar;
        float4 a0, a1;
        if (gr < Nn) {
            const float4* ap = (const float4*)&A[gr * FIN + k0 + ah * 8];
            a0 = ap[0]; a1 = ap[1];
        } else {
            a0 = make_float4(0.f, 0.f, 0.f, 0.f); a1 = a0;
        }
        As[ah * 8 + 0][ar] = a0.x; As[ah * 8 + 1][ar] = a0.y;
        As[ah * 8 + 2][ar] = a0.z; As[ah * 8 + 3][ar] = a0.w;
        As[ah * 8 + 4][ar] = a1.x; As[ah * 8 + 5][ar] = a1.y;
        As[ah * 8 + 6][ar] = a1.z; As[ah * 8 + 7][ar] = a1.w;

        const float4* bp = (const float4*)&W[(k0 + bk) * HD + bc];
        float4 b0 = bp[0], b1 = bp[1];
        *(float4*)&Bs[bk][bc] = b0;
        *(float4*)&Bs[bk][bc + 4] = b1;
        __syncthreads();
        #pragma unroll
        for (int kk = 0; kk < BK; kk++) {
            float a[8], b[8];
            #pragma unroll
            for (int i = 0; i < 8; i++) a[i] = As[kk][ty * 8 + i];
            #pragma unroll
            for (int j = 0; j < 8; j++) b[j] = Bs[kk][tx * 8 + j];
            #pragma unroll
            for (int i = 0; i < 8; i++)
                #pragma unroll
                for (int j = 0; j < 8; j++) acc[i][j] += a[i] * b[j];
        }
        __syncthreads();
    }
    #pragma unroll
    for (int i = 0; i < 8; i++) {
        int r = row0 + ty * 8 + i;
        if (r >= Nn) continue;
        #pragma unroll
        for (int j = 0; j < 8; j++) {
            float v = acc[i][j];
            if (blockIdx.y) v += bias[tx * 8 + j];
            Out[r * HD + tx * 8 + j] = v;
        }
    }
}

// ---------------- attention projections: a_src/a_dst [N,2] -------------------
__global__ void attn_gemm_kernel(const float* __restrict__ A,
                                 const float* __restrict__ Wsrc,
                                 const float* __restrict__ Wdst)
{
    int gw = (blockIdx.x * blockDim.x + threadIdx.x) >> 5;
    int lane = threadIdx.x & 31;
    if (gw >= Nn * 4) return;
    int n = gw >> 2;
    int q = gw & 3;
    int hh = q & 1;
    const float* W = (q < 2) ? Wsrc : Wdst;
    float s = 0.f;
    #pragma unroll
    for (int j = 0; j < FIN / 32; j++) {
        int k = lane + 32 * j;
        s += A[n * FIN + k] * W[k * 2 + hh];
    }
    #pragma unroll
    for (int o = 16; o; o >>= 1) s += __shfl_xor_sync(0xffffffffu, s, o);
    if (lane == 0) {
        if (q < 2) g_asrc[n * 2 + hh] = s;
        else       g_adst[n * 2 + hh] = s;
    }
}

// ---------------- init: zero counters + softmax sums -------------------------
__global__ void init_kernel() {
    int i = blockIdx.x * blockDim.x + threadIdx.x;
    if (i < Nn) {
        g_cnt[i] = 0;
        ((float2*)g_sumd)[i] = make_float2(0.f, 0.f);
        ((float2*)g_sums)[i] = make_float2(0.f, 0.f);
    }
}

// ---------------- CSR build --------------------------------------------------
__global__ void hist_kernel(const int* __restrict__ dst) {
    int e = blockIdx.x * blockDim.x + threadIdx.x;
    if (e < Ee) atomicAdd(&g_cnt[dst[e]], 1);
}

__global__ __launch_bounds__(1024) void scan_kernel() {
    __shared__ int part[1024];
    const int CH = (Nn + 1023) / 1024;
    int t = threadIdx.x;
    int start = t * CH;
    int s = 0;
    for (int i = 0; i < CH; i++) {
        int idx = start + i;
        if (idx < Nn) s += g_cnt[idx];
    }
    part[t] = s;
    __syncthreads();
    for (int off = 1; off < 1024; off <<= 1) {
        int v = (t >= off) ? part[t - off] : 0;
        __syncthreads();
        part[t] += v;
        __syncthreads();
    }
    int base = (t == 0) ? 0 : part[t - 1];
    for (int i = 0; i < CH; i++) {
        int idx = start + i;
        if (idx < Nn) {
            g_rp[idx] = base;
            g_cur[idx] = base;
            base += g_cnt[idx];
        }
    }
    if (t == 1023) g_rp[Nn] = Ee;
}

// ---------------- place + edge logits/exp + segment sums (fused) -------------
__global__ void place_edge_kernel(const int* __restrict__ src, const int* __restrict__ dst) {
    int e = blockIdx.x * blockDim.x + threadIdx.x;
    if (e >= Ee) return;
    int s = src[e], d = dst[e];
    int pos = atomicAdd(&g_cur[d], 1);
    g_srcc[pos] = s;
    float2 as = ((const float2*)g_asrc)[s];
    float2 ad = ((const float2*)g_adst)[d];
    float e0 = __expf(leaky(as.x + ad.x));
    float e1 = __expf(leaky(as.y + ad.y));
    ((float2*)g_acsr)[pos] = make_float2(e0, e1);
    atomicAdd(&g_sumd[d * 2], e0);     atomicAdd(&g_sumd[d * 2 + 1], e1);
    atomicAdd(&g_sums[s * 2], e0);     atomicAdd(&g_sums[s * 2 + 1], e1);
}

// ---------------- final symmetric weights, node-parallel over CSR ------------
__global__ void edgeB_kernel() {
    int gw = (blockIdx.x * blockDim.x + threadIdx.x) >> 5;
    int lane = threadIdx.x & 31;
    if (gw >= Nn) return;
    int b = g_rp[gw], e = g_rp[gw + 1];
    if (b == e) return;
    float2 sd = ((const float2*)g_sumd)[gw];
    float rd0 = 1.f / sd.x, rd1 = 1.f / sd.y;
    for (int pos = b + lane; pos < e; pos += 32) {
        int s = g_srcc[pos];
        float2 ex = ((const float2*)g_acsr)[pos];
        float2 ss = ((const float2*)g_sums)[s];
        float a0 = sqrtf(fmaxf(ex.x * rd0, EPSf) * fmaxf(ex.x / ss.x, EPSf));
        float a1 = sqrtf(fmaxf(ex.y * rd1, EPSf) * fmaxf(ex.y / ss.y, EPSf));
        ((float2*)g_acsr)[pos] = make_float2(a0, a1);
    }
}

// ---------------- shared feat_trans epilogue helper --------------------------
__device__ __forceinline__ float4 feat_trans4(
    float4 acc, int lane, int k,
    const float* __restrict__ scale, const float* __restrict__ offset,
    const float* __restrict__ pemb)
{
    float s = acc.x + acc.y + acc.z + acc.w;
    float sq = acc.x * acc.x + acc.y * acc.y + acc.z * acc.z + acc.w * acc.w;
    #pragma unroll
    for (int o = 8; o; o >>= 1) {
        s  += __shfl_xor_sync(0xffffffffu, s,  o, 16);
        sq += __shfl_xor_sync(0xffffffffu, sq, o, 16);
    }
    float mean = s * (1.f / 64.f);
    float var = sq * (1.f / 64.f) - mean * mean + EPSf;
    float rs = rsqrtf(var);
    float4 sc = ((const float4*)scale)[k * 32 + lane];
    float4 of = ((const float4*)offset)[k * 32 + lane];
    float4 pe = ((const float4*)pemb)[k * 32 + lane];
    float4 y;
    y.x = (acc.x - mean) * sc.x * rs + of.x + pe.x;
    y.y = (acc.y - mean) * sc.y * rs + of.y + pe.y;
    y.z = (acc.z - mean) * sc.z * rs + of.z + pe.z;
    y.w = (acc.w - mean) * sc.w * rs + of.w + pe.w;
    return y;
}

__device__ __forceinline__ void store_half4(__half* __restrict__ out16,
                                            int idx4, float4 v)
{
    uint2 raw;
    *(__half2*)&raw.x = __floats2half2_rn(v.x, v.y);
    *(__half2*)&raw.y = __floats2half2_rn(v.z, v.w);
    ((uint2*)out16)[idx4] = raw;
}

// ---------------- ft0: feat_trans(h_src,0) -> h0t, plus fp16 copy of h_src ---
__global__ void ft0_kernel(const float* __restrict__ scale,
                           const float* __restrict__ offset,
                           const float* __restrict__ pemb)
{
    int gw = (blockIdx.x * blockDim.x + threadIdx.x) >> 5;
    int lane = threadIdx.x & 31;
    if (gw >= Nn) return;
    float4 x = ((const float4*)g_hsrc)[gw * 32 + lane];
    store_half4(g_h16[0], gw * 32 + lane, x);
    ((float4*)g_hs[2])[gw * 32 + lane] = feat_trans4(x, lane, 0, scale, offset, pemb);
}

// ---------------- fp16 gather core with warp register caching ----------------
// Lanes cooperatively load 32 (src, a) pairs coalesced, then shuffle-broadcast
// each edge to all lanes; row-gather loads within a chunk are independent.
__device__ __forceinline__ float4 gather_row(const __half* __restrict__ in16,
                                             int b, int e, int lane, int hh)
{
    const uint2* in = (const uint2*)in16;
    float4 acc = make_float4(0.f, 0.f, 0.f, 0.f);
    for (int base = b; base < e; base += 32) {
        int cnt = e - base;         // >0
        int sj = 0;
        float2 aj = make_float2(0.f, 0.f);
        if (base + lane < e) {
            sj = g_srcc[base + lane];
            aj = ((const float2*)g_acsr)[base + lane];
        }
        float av = hh ? aj.y : aj.x;   // not used directly; keeps both halves live
        (void)av;
        if (cnt >= 32) {
            #pragma unroll 8
            for (int j = 0; j < 32; j++) {
                int s = __shfl_sync(0xffffffffu, sj, j);
                float a0 = __shfl_sync(0xffffffffu, aj.x, j);
                float a1 = __shfl_sync(0xffffffffu, aj.y, j);
                float a = hh ? a1 : a0;
                uint2 raw = in[s * 32 + lane];
                float2 lo = __half22float2(*(const __half2*)&raw.x);
                float2 hi = __half22float2(*(const __half2*)&raw.y);
                acc.x += a * lo.x; acc.y += a * lo.y;
                acc.z += a * hi.x; acc.w += a * hi.y;
            }
        } else {
            for (int j = 0; j < cnt; j++) {
                int s = __shfl_sync(0xffffffffu, sj, j);
                float a0 = __shfl_sync(0xffffffffu, aj.x, j);
                float a1 = __shfl_sync(0xffffffffu, aj.y, j);
                float a = hh ? a1 : a0;
                uint2 raw = in[s * 32 + lane];
                float2 lo = __half22float2(*(const __half2*)&raw.x);
                float2 hi = __half22float2(*(const __half2*)&raw.y);
                acc.x += a * lo.x; acc.y += a * lo.y;
                acc.z += a * hi.x; acc.w += a * hi.y;
            }
        }
    }
    return acc;
}

// ---------------- diffusion hop (gather) + fused feat_trans ------------------
// Buffer selection via integer selectors resolved in DEVICE code only.
__global__ __launch_bounds__(256) void hop_kernel(
    int in_sel, int out_sel, int ts_sel, int k,
    const float* __restrict__ scale, const float* __restrict__ offset,
    const float* __restrict__ pemb)
{
    int gw = (blockIdx.x * blockDim.x + threadIdx.x) >> 5;
    int lane = threadIdx.x & 31;
    if (gw >= Nn) return;
    const __half* in16 = g_h16[in_sel];
    __half* out16 = g_h16[out_sel];
    int hh = lane >> 4;
    int b = g_rp[gw], e = g_rp[gw + 1];
    float4 acc = gather_row(in16, b, e, lane, hh);
    store_half4(out16, gw * 32 + lane, acc);
    ((float4*)g_hs[ts_sel])[gw * 32 + lane] =
        feat_trans4(acc, lane, k, scale, offset, pemb);
}

// ---------------- hop 3 + feat_trans + hop attention + residual --------------
__global__ __launch_bounds__(256) void hop3_final_kernel(
    const float* __restrict__ scale, const float* __restrict__ offset,
    const float* __restrict__ pemb,
    const float* __restrict__ attn_l, const float* __restrict__ attn_r,
    float* __restrict__ out)
{
    int gw = (blockIdx.x * blockDim.x + threadIdx.x) >> 5;
    int lane = threadIdx.x & 31;
    if (gw >= Nn) return;
    const __half* in16 = g_h16[2];
    int hh = lane >> 4;
    int b = g_rp[gw], e = g_rp[gw + 1];
    float4 acc = gather_row(in16, b, e, lane, hh);
    float4 s2 = feat_trans4(acc, lane, 3, scale, offset, pemb);

    float4 s0 = ((const float4*)g_hs[0])[gw * 32 + lane];
    float4 s1 = ((const float4*)g_hs[1])[gw * 32 + lane];
    float4 h0 = ((const float4*)g_hs[2])[gw * 32 + lane];
    float4 al4 = ((const float4*)attn_l)[lane];
    float4 ar4 = ((const float4*)attn_r)[lane];

    float al = h0.x * al4.x + h0.y * al4.y + h0.z * al4.z + h0.w * al4.w;
    float w0 = s0.x * ar4.x + s0.y * ar4.y + s0.z * ar4.z + s0.w * ar4.w;
    float w1 = s1.x * ar4.x + s1.y * ar4.y + s1.z * ar4.z + s1.w * ar4.w;
    float w2 = s2.x * ar4.x + s2.y * ar4.y + s2.z * ar4.z + s2.w * ar4.w;
    #pragma unroll
    for (int o = 8; o; o >>= 1) {
        al += __shfl_xor_sync(0xffffffffu, al, o, 16);
        w0 += __shfl_xor_sync(0xffffffffu, w0, o, 16);
        w1 += __shfl_xor_sync(0xffffffffu, w1, o, 16);
        w2 += __shfl_xor_sync(0xffffffffu, w2, o, 16);
    }
    float l0 = leaky(w0 + al), l1 = leaky(w1 + al), l2 = leaky(w2 + al);
    float m = fmaxf(l0, fmaxf(l1, l2));
    float e0 = __expf(l0 - m), e1 = __expf(l1 - m), e2 = __expf(l2 - m);
    float inv = 1.f / (e0 + e1 + e2);
    e0 *= inv; e1 *= inv; e2 *= inv;

    float4 hd = ((const float4*)g_hdst)[gw * 32 + lane];
    float4 o4;
    o4.x = s0.x * e0 + s1.x * e1 + s2.x * e2 + hd.x;
    o4.y = s0.y * e0 + s1.y * e1 + s2.y * e2 + hd.y;
    o4.z = s0.z * e0 + s1.z * e1 + s2.z * e2 + hd.z;
    o4.w = s0.w * e0 + s1.w * e1 + s2.w * e2 + hd.w;
    ((float4*)out)[gw * 32 + lane] = o4;
}

// ---------------- launch ------------------------------------------------------
extern "C" void kernel_launch(void* const* d_in, const int* in_sizes, int n_in,
                              void* d_out, int out_size)
{
    const float* feat  = (const float*)d_in[0];
    const int*   src   = (const int*)d_in[1];
    const int*   dst   = (const int*)d_in[2];
    const float* Wsrc  = (const float*)d_in[3];
    const float* Wdst  = (const float*)d_in[4];
    const float* bdst  = (const float*)d_in[5];
    const float* Wasrc = (const float*)d_in[6];
    const float* Wadst = (const float*)d_in[7];
    const float* scale = (const float*)d_in[8];
    const float* offs  = (const float*)d_in[9];
    const float* pemb  = (const float*)d_in[10];
    const float* hal   = (const float*)d_in[11];
    const float* har   = (const float*)d_in[12];
    float* out = (float*)d_out;

    const int EG = (Ee + 255) / 256;
    const int NWG = (Nn * 32 + 255) / 256;

    // projections
    gemm_h_kernel<<<dim3((Nn + 127) / 128, 2), 256>>>(feat, Wsrc, Wdst, bdst);
    attn_gemm_kernel<<<(Nn * 4 * 32 + 255) / 256, 256>>>(feat, Wasrc, Wadst);

    // CSR build + fused edge logits/exp/sums
    init_kernel<<<(Nn + 255) / 256, 256>>>();
    hist_kernel<<<EG, 256>>>(dst);
    scan_kernel<<<1, 1024>>>();
    place_edge_kernel<<<EG, 256>>>(src, dst);
    edgeB_kernel<<<NWG, 256>>>();

    // h0 = feat_trans(h_src, 0) + fp16 copy of h_src
    ft0_kernel<<<NWG, 256>>>(scale, offs, pemb);

    // diffusion hops (fp16 gather, fp32 accumulate, fused feat_trans)
    hop_kernel<<<NWG, 256>>>(0, 1, 0, 1, scale, offs, pemb);
    hop_kernel<<<NWG, 256>>>(1, 2, 1, 2, scale, offs, pemb);
    hop3_final_kernel<<<NWG, 256>>>(scale, offs, pemb, hal, har, out);
}

// round 10
// speedup vs baseline: 1.9236x; 1.1020x over previous
#include <cuda_runtime.h>
#include <cuda_fp16.h>
#include <mma.h>

using namespace nvcuda;

#define Nn 50000
#define Ee 1600000
#define FIN 256
#define HD 128
#define NEG 0.2f
#define EPSf 1e-9f

// ---------------- scratch (static device globals) ----------------------------
__device__ float  g_hsrc[Nn * HD];        // fp32 h_src
__device__ float  g_hdst[Nn * HD];        // residual branch (bias added at end)
__device__ __half g_feat16[Nn * FIN];     // fp16 feat for TC GEMM
__device__ __half g_w16[2][FIN * HD];     // fp16 W_src / W_dst
__device__ __half g_h16[3][Nn * HD];      // fp16 gather sources
__device__ float  g_hs[3][Nn * HD];       // [0]=hs1t, [1]=hs2t, [2]=h0t
__device__ float  g_asrc[Nn * 2];
__device__ float  g_adst[Nn * 2];
__device__ float  g_acsr[Ee * 2];
__device__ int    g_srcc[Ee];
__device__ int    g_cnt[Nn];
__device__ int    g_rp[Nn + 1];
__device__ int    g_cur[Nn];
__device__ float  g_sumd[Nn * 2];
__device__ float  g_sums[Nn * 2];

__device__ __forceinline__ float leaky(float x) { return x > 0.f ? x : NEG * x; }

// ---------------- fused: feat fp32->fp16 + attention projections -------------
__global__ void convert_attn_kernel(const float* __restrict__ feat,
                                    const float* __restrict__ Wasrc,
                                    const float* __restrict__ Wadst)
{
    int gw = (blockIdx.x * blockDim.x + threadIdx.x) >> 5;
    int lane = threadIdx.x & 31;
    if (gw >= Nn) return;
    const float4* frow = (const float4*)&feat[gw * FIN];
    float4 x0 = frow[lane];        // cols 4*lane..+3
    float4 x1 = frow[lane + 32];   // cols 128+4*lane..+3
    uint2 r0, r1;
    *(__half2*)&r0.x = __floats2half2_rn(x0.x, x0.y);
    *(__half2*)&r0.y = __floats2half2_rn(x0.z, x0.w);
    *(__half2*)&r1.x = __floats2half2_rn(x1.x, x1.y);
    *(__half2*)&r1.y = __floats2half2_rn(x1.z, x1.w);
    ((uint2*)g_feat16)[gw * 64 + lane] = r0;
    ((uint2*)g_feat16)[gw * 64 + 32 + lane] = r1;

    int c0 = lane * 4, c1 = 128 + lane * 4;
    float s0 = 0.f, s1 = 0.f, d0 = 0.f, d1 = 0.f;
    #pragma unroll
    for (int j = 0; j < 4; j++) {
        float xa = (&x0.x)[j];
        float2 ws = ((const float2*)Wasrc)[c0 + j];
        float2 wd = ((const float2*)Wadst)[c0 + j];
        s0 += xa * ws.x; s1 += xa * ws.y;
        d0 += xa * wd.x; d1 += xa * wd.y;
        float xb = (&x1.x)[j];
        float2 ws1 = ((const float2*)Wasrc)[c1 + j];
        float2 wd1 = ((const float2*)Wadst)[c1 + j];
        s0 += xb * ws1.x; s1 += xb * ws1.y;
        d0 += xb * wd1.x; d1 += xb * wd1.y;
    }
    #pragma unroll
    for (int o = 16; o; o >>= 1) {
        s0 += __shfl_xor_sync(0xffffffffu, s0, o);
        s1 += __shfl_xor_sync(0xffffffffu, s1, o);
        d0 += __shfl_xor_sync(0xffffffffu, d0, o);
        d1 += __shfl_xor_sync(0xffffffffu, d1, o);
    }
    if (lane == 0) {
        ((float2*)g_asrc)[gw] = make_float2(s0, s1);
        ((float2*)g_adst)[gw] = make_float2(d0, d1);
    }
}

// ---------------- W fp32 -> fp16 (tiny) --------------------------------------
__global__ void wconv_kernel(const float* __restrict__ Wsrc,
                             const float* __restrict__ Wdst)
{
    int i = blockIdx.x * blockDim.x + threadIdx.x;
    if (i < FIN * HD / 2) {
        float2 a = ((const float2*)Wsrc)[i];
        float2 b = ((const float2*)Wdst)[i];
        *(__half2*)&g_w16[0][i * 2] = __floats2half2_rn(a.x, a.y);
        *(__half2*)&g_w16[1][i * 2] = __floats2half2_rn(b.x, b.y);
    }
}

// ---------------- tensor-core GEMM: Out = feat16 @ W16 -----------------------
// grid.x = ceil(Nn/128); grid.y in 0..3: bit0 = which W, bit1 = column half.
__global__ __launch_bounds__(256) void gemm_tc_kernel()
{
    __shared__ __half Bs[FIN * 64];        // 32 KB: W[k][nhalf*64 + n]
    int wsel = blockIdx.y & 1;
    int nhalf = blockIdx.y >> 1;
    const uint2* wsrc = (const uint2*)g_w16[wsel];
    uint2* bs = (uint2*)Bs;
    for (int i = threadIdx.x; i < FIN * 16; i += 256) {
        int r = i >> 4, c = i & 15;
        bs[r * 16 + c] = wsrc[r * 32 + nhalf * 16 + c];
    }
    __syncthreads();
    int wid = threadIdx.x >> 5;
    int row0 = blockIdx.x * 128 + wid * 16;
    if (row0 >= Nn) return;                // Nn % 16 == 0, whole-warp tiles

    wmma::fragment<wmma::accumulator, 16, 16, 16, float> acc[4];
    #pragma unroll
    for (int n = 0; n < 4; n++) wmma::fill_fragment(acc[n], 0.f);
    const __half* arow = g_feat16 + row0 * FIN;
    #pragma unroll 4
    for (int kt = 0; kt < 16; kt++) {
        wmma::fragment<wmma::matrix_a, 16, 16, 16, __half, wmma::row_major> af;
        wmma::load_matrix_sync(af, arow + kt * 16, FIN);
        #pragma unroll
        for (int n = 0; n < 4; n++) {
            wmma::fragment<wmma::matrix_b, 16, 16, 16, __half, wmma::row_major> bf;
            wmma::load_matrix_sync(bf, Bs + kt * 16 * 64 + n * 16, 64);
            wmma::mma_sync(acc[n], af, bf, acc[n]);
        }
    }
    float* Out = wsel ? g_hdst : g_hsrc;
    #pragma unroll
    for (int n = 0; n < 4; n++)
        wmma::store_matrix_sync(Out + row0 * HD + nhalf * 64 + n * 16,
                                acc[n], HD, wmma::mem_row_major);
}

// ---------------- init: zero counters + softmax sums -------------------------
__global__ void init_kernel() {
    int i = blockIdx.x * blockDim.x + threadIdx.x;
    if (i < Nn) {
        g_cnt[i] = 0;
        ((float2*)g_sumd)[i] = make_float2(0.f, 0.f);
        ((float2*)g_sums)[i] = make_float2(0.f, 0.f);
    }
}

// ---------------- CSR build --------------------------------------------------
__global__ void hist_kernel(const int* __restrict__ dst) {
    int e = blockIdx.x * blockDim.x + threadIdx.x;
    if (e < Ee) atomicAdd(&g_cnt[dst[e]], 1);
}

__global__ __launch_bounds__(1024) void scan_kernel() {
    __shared__ int part[1024];
    const int CH = (Nn + 1023) / 1024;
    int t = threadIdx.x;
    int start = t * CH;
    int s = 0;
    for (int i = 0; i < CH; i++) {
        int idx = start + i;
        if (idx < Nn) s += g_cnt[idx];
    }
    part[t] = s;
    __syncthreads();
    for (int off = 1; off < 1024; off <<= 1) {
        int v = (t >= off) ? part[t - off] : 0;
        __syncthreads();
        part[t] += v;
        __syncthreads();
    }
    int base = (t == 0) ? 0 : part[t - 1];
    for (int i = 0; i < CH; i++) {
        int idx = start + i;
        if (idx < Nn) {
            g_rp[idx] = base;
            g_cur[idx] = base;
            base += g_cnt[idx];
        }
    }
    if (t == 1023) g_rp[Nn] = Ee;
}

// ---------------- place + edge logits/exp + segment sums (fused) -------------
__global__ void place_edge_kernel(const int* __restrict__ src, const int* __restrict__ dst) {
    int e = blockIdx.x * blockDim.x + threadIdx.x;
    if (e >= Ee) return;
    int s = src[e], d = dst[e];
    int pos = atomicAdd(&g_cur[d], 1);
    g_srcc[pos] = s;
    float2 as = ((const float2*)g_asrc)[s];
    float2 ad = ((const float2*)g_adst)[d];
    float e0 = __expf(leaky(as.x + ad.x));
    float e1 = __expf(leaky(as.y + ad.y));
    ((float2*)g_acsr)[pos] = make_float2(e0, e1);
    atomicAdd(&g_sumd[d * 2], e0);     atomicAdd(&g_sumd[d * 2 + 1], e1);
    atomicAdd(&g_sums[s * 2], e0);     atomicAdd(&g_sums[s * 2 + 1], e1);
}

// ---------------- final symmetric weights, node-parallel over CSR ------------
__global__ void edgeB_kernel() {
    int gw = (blockIdx.x * blockDim.x + threadIdx.x) >> 5;
    int lane = threadIdx.x & 31;
    if (gw >= Nn) return;
    int b = g_rp[gw], e = g_rp[gw + 1];
    if (b == e) return;
    float2 sd = ((const float2*)g_sumd)[gw];
    float rd0 = 1.f / sd.x, rd1 = 1.f / sd.y;
    for (int pos = b + lane; pos < e; pos += 32) {
        int s = g_srcc[pos];
        float2 ex = ((const float2*)g_acsr)[pos];
        float2 ss = ((const float2*)g_sums)[s];
        float a0 = sqrtf(fmaxf(ex.x * rd0, EPSf) * fmaxf(ex.x / ss.x, EPSf));
        float a1 = sqrtf(fmaxf(ex.y * rd1, EPSf) * fmaxf(ex.y / ss.y, EPSf));
        ((float2*)g_acsr)[pos] = make_float2(a0, a1);
    }
}

// ---------------- shared feat_trans epilogue helper --------------------------
__device__ __forceinline__ float4 feat_trans4(
    float4 acc, int lane, int k,
    const float* __restrict__ scale, const float* __restrict__ offset,
    const float* __restrict__ pemb)
{
    float s = acc.x + acc.y + acc.z + acc.w;
    float sq = acc.x * acc.x + acc.y * acc.y + acc.z * acc.z + acc.w * acc.w;
    #pragma unroll
    for (int o = 8; o; o >>= 1) {
        s  += __shfl_xor_sync(0xffffffffu, s,  o, 16);
        sq += __shfl_xor_sync(0xffffffffu, sq, o, 16);
    }
    float mean = s * (1.f / 64.f);
    float var = sq * (1.f / 64.f) - mean * mean + EPSf;
    float rs = rsqrtf(var);
    float4 sc = ((const float4*)scale)[k * 32 + lane];
    float4 of = ((const float4*)offset)[k * 32 + lane];
    float4 pe = ((const float4*)pemb)[k * 32 + lane];
    float4 y;
    y.x = (acc.x - mean) * sc.x * rs + of.x + pe.x;
    y.y = (acc.y - mean) * sc.y * rs + of.y + pe.y;
    y.z = (acc.z - mean) * sc.z * rs + of.z + pe.z;
    y.w = (acc.w - mean) * sc.w * rs + of.w + pe.w;
    return y;
}

__device__ __forceinline__ void store_half4(__half* __restrict__ out16,
                                            int idx4, float4 v)
{
    uint2 raw;
    *(__half2*)&raw.x = __floats2half2_rn(v.x, v.y);
    *(__half2*)&raw.y = __floats2half2_rn(v.z, v.w);
    ((uint2*)out16)[idx4] = raw;
}

// ---------------- ft0: feat_trans(h_src,0) -> h0t, plus fp16 copy of h_src ---
__global__ void ft0_kernel(const float* __restrict__ scale,
                           const float* __restrict__ offset,
                           const float* __restrict__ pemb)
{
    int gw = (blockIdx.x * blockDim.x + threadIdx.x) >> 5;
    int lane = threadIdx.x & 31;
    if (gw >= Nn) return;
    float4 x = ((const float4*)g_hsrc)[gw * 32 + lane];
    store_half4(g_h16[0], gw * 32 + lane, x);
    ((float4*)g_hs[2])[gw * 32 + lane] = feat_trans4(x, lane, 0, scale, offset, pemb);
}

// ---------------- fp16 gather core with warp register caching ----------------
__device__ __forceinline__ float4 gather_row(const __half* __restrict__ in16,
                                             int b, int e, int lane, int hh)
{
    const uint2* in = (const uint2*)in16;
    float4 acc = make_float4(0.f, 0.f, 0.f, 0.f);
    for (int base = b; base < e; base += 32) {
        int cnt = e - base;
        int sj = 0;
        float2 aj = make_float2(0.f, 0.f);
        if (base + lane < e) {
            sj = g_srcc[base + lane];
            aj = ((const float2*)g_acsr)[base + lane];
        }
        if (cnt >= 32) {
            #pragma unroll 8
            for (int j = 0; j < 32; j++) {
                int s = __shfl_sync(0xffffffffu, sj, j);
                float a0 = __shfl_sync(0xffffffffu, aj.x, j);
                float a1 = __shfl_sync(0xffffffffu, aj.y, j);
                float a = hh ? a1 : a0;
                uint2 raw = in[s * 32 + lane];
                float2 lo = __half22float2(*(const __half2*)&raw.x);
                float2 hi = __half22float2(*(const __half2*)&raw.y);
                acc.x += a * lo.x; acc.y += a * lo.y;
                acc.z += a * hi.x; acc.w += a * hi.y;
            }
        } else {
            for (int j = 0; j < cnt; j++) {
                int s = __shfl_sync(0xffffffffu, sj, j);
                float a0 = __shfl_sync(0xffffffffu, aj.x, j);
                float a1 = __shfl_sync(0xffffffffu, aj.y, j);
                float a = hh ? a1 : a0;
                uint2 raw = in[s * 32 + lane];
                float2 lo = __half22float2(*(const __half2*)&raw.x);
                float2 hi = __half22float2(*(const __half2*)&raw.y);
                acc.x += a * lo.x; acc.y += a * lo.y;
                acc.z += a * hi.x; acc.w += a * hi.y;
            }
        }
    }
    return acc;
}

// ---------------- diffusion hop (gather) + fused feat_trans ------------------
__global__ __launch_bounds__(256) void hop_kernel(
    int in_sel, int out_sel, int ts_sel, int k,
    const float* __restrict__ scale, const float* __restrict__ offset,
    const float* __restrict__ pemb)
{
    int gw = (blockIdx.x * blockDim.x + threadIdx.x) >> 5;
    int lane = threadIdx.x & 31;
    if (gw >= Nn) return;
    const __half* in16 = g_h16[in_sel];
    __half* out16 = g_h16[out_sel];
    int hh = lane >> 4;
    int b = g_rp[gw], e = g_rp[gw + 1];
    float4 acc = gather_row(in16, b, e, lane, hh);
    store_half4(out16, gw * 32 + lane, acc);
    ((float4*)g_hs[ts_sel])[gw * 32 + lane] =
        feat_trans4(acc, lane, k, scale, offset, pemb);
}

// ---------------- hop 3 + feat_trans + hop attention + residual + bias -------
__global__ __launch_bounds__(256) void hop3_final_kernel(
    const float* __restrict__ scale, const float* __restrict__ offset,
    const float* __restrict__ pemb,
    const float* __restrict__ attn_l, const float* __restrict__ attn_r,
    const float* __restrict__ bias,
    float* __restrict__ out)
{
    int gw = (blockIdx.x * blockDim.x + threadIdx.x) >> 5;
    int lane = threadIdx.x & 31;
    if (gw >= Nn) return;
    const __half* in16 = g_h16[2];
    int hh = lane >> 4;
    int b = g_rp[gw], e = g_rp[gw + 1];
    float4 acc = gather_row(in16, b, e, lane, hh);
    float4 s2 = feat_trans4(acc, lane, 3, scale, offset, pemb);

    float4 s0 = ((const float4*)g_hs[0])[gw * 32 + lane];
    float4 s1 = ((const float4*)g_hs[1])[gw * 32 + lane];
    float4 h0 = ((const float4*)g_hs[2])[gw * 32 + lane];
    float4 al4 = ((const float4*)attn_l)[lane];
    float4 ar4 = ((const float4*)attn_r)[lane];

    float al = h0.x * al4.x + h0.y * al4.y + h0.z * al4.z + h0.w * al4.w;
    float w0 = s0.x * ar4.x + s0.y * ar4.y + s0.z * ar4.z + s0.w * ar4.w;
    float w1 = s1.x * ar4.x + s1.y * ar4.y + s1.z * ar4.z + s1.w * ar4.w;
    float w2 = s2.x * ar4.x + s2.y * ar4.y + s2.z * ar4.z + s2.w * ar4.w;
    #pragma unroll
    for (int o = 8; o; o >>= 1) {
        al += __shfl_xor_sync(0xffffffffu, al, o, 16);
        w0 += __shfl_xor_sync(0xffffffffu, w0, o, 16);
        w1 += __shfl_xor_sync(0xffffffffu, w1, o, 16);
        w2 += __shfl_xor_sync(0xffffffffu, w2, o, 16);
    }
    float l0 = leaky(w0 + al), l1 = leaky(w1 + al), l2 = leaky(w2 + al);
    float m = fmaxf(l0, fmaxf(l1, l2));
    float e0 = __expf(l0 - m), e1 = __expf(l1 - m), e2 = __expf(l2 - m);
    float inv = 1.f / (e0 + e1 + e2);
    e0 *= inv; e1 *= inv; e2 *= inv;

    float4 hd = ((const float4*)g_hdst)[gw * 32 + lane];
    float4 b4 = ((const float4*)bias)[lane];
    float4 o4;
    o4.x = s0.x * e0 + s1.x * e1 + s2.x * e2 + hd.x + b4.x;
    o4.y = s0.y * e0 + s1.y * e1 + s2.y * e2 + hd.y + b4.y;
    o4.z = s0.z * e0 + s1.z * e1 + s2.z * e2 + hd.z + b4.z;
    o4.w = s0.w * e0 + s1.w * e1 + s2.w * e2 + hd.w + b4.w;
    ((float4*)out)[gw * 32 + lane] = o4;
}

// ---------------- launch ------------------------------------------------------
extern "C" void kernel_launch(void* const* d_in, const int* in_sizes, int n_in,
                              void* d_out, int out_size)
{
    const float* feat  = (const float*)d_in[0];
    const int*   src   = (const int*)d_in[1];
    const int*   dst   = (const int*)d_in[2];
    const float* Wsrc  = (const float*)d_in[3];
    const float* Wdst  = (const float*)d_in[4];
    const float* bdst  = (const float*)d_in[5];
    const float* Wasrc = (const float*)d_in[6];
    const float* Wadst = (const float*)d_in[7];
    const float* scale = (const float*)d_in[8];
    const float* offs  = (const float*)d_in[9];
    const float* pemb  = (const float*)d_in[10];
    const float* hal   = (const float*)d_in[11];
    const float* har   = (const float*)d_in[12];
    float* out = (float*)d_out;

    const int EG = (Ee + 255) / 256;
    const int NWG = (Nn * 32 + 255) / 256;

    // fp16 conversion + attention projections (one pass over feat)
    convert_attn_kernel<<<NWG, 256>>>(feat, Wasrc, Wadst);
    wconv_kernel<<<(FIN * HD / 2 + 255) / 256, 256>>>(Wsrc, Wdst);

    // tensor-core projections
    gemm_tc_kernel<<<dim3((Nn + 127) / 128, 4), 256>>>();

    // CSR build + fused edge logits/exp/sums
    init_kernel<<<(Nn + 255) / 256, 256>>>();
    hist_kernel<<<EG, 256>>>(dst);
    scan_kernel<<<1, 1024>>>();
    place_edge_kernel<<<EG, 256>>>(src, dst);
    edgeB_kernel<<<NWG, 256>>>();

    // h0 = feat_trans(h_src, 0) + fp16 copy of h_src
    ft0_kernel<<<NWG, 256>>>(scale, offs, pemb);

    // diffusion hops (fp16 gather, fp32 accumulate, fused feat_trans)
    hop_kernel<<<NWG, 256>>>(0, 1, 0, 1, scale, offs, pemb);
    hop_kernel<<<NWG, 256>>>(1, 2, 1, 2, scale, offs, pemb);
    hop3_final_kernel<<<NWG, 256>>>(scale, offs, pemb, hal, har, bdst, out);
}

// round 11
// speedup vs baseline: 1.9289x; 1.0028x over previous
#include <cuda_runtime.h>
#include <cuda_fp16.h>
#include <mma.h>

using namespace nvcuda;

#define Nn 50000
#define Ee 1600000
#define FIN 256
#define HD 128
#define NEG 0.2f
#define EPSf 1e-9f

// ---------------- scratch (static device globals) ----------------------------
__device__ float  g_hsrc[Nn * HD];        // fp32 h_src
__device__ float  g_hdst[Nn * HD];        // residual branch (bias added at end)
__device__ __half g_feat16[Nn * FIN];     // fp16 feat for TC GEMM
__device__ __half g_w16[2][FIN * HD];     // fp16 W_src / W_dst
__device__ __half g_h16[3][Nn * HD];      // fp16 gather sources
__device__ float  g_hs[3][Nn * HD];       // [0]=hs1t, [1]=hs2t, [2]=h0t
__device__ float  g_asrc[Nn * 2];
__device__ float  g_adst[Nn * 2];
__device__ float  g_acsr[Ee * 2];         // CSR: exp(logit) then (after hop1) weight
__device__ int    g_srcc[Ee];
__device__ int    g_cnt[Nn];
__device__ int    g_rp[Nn + 1];
__device__ int    g_cur[Nn];
__device__ float  g_sumd[Nn * 2];
__device__ float  g_sums[Nn * 2];

__device__ __forceinline__ float leaky(float x) { return x > 0.f ? x : NEG * x; }

// ---------------- fused: feat fp32->fp16 + attention projections -------------
__global__ void convert_attn_kernel(const float* __restrict__ feat,
                                    const float* __restrict__ Wasrc,
                                    const float* __restrict__ Wadst)
{
    int gw = (blockIdx.x * blockDim.x + threadIdx.x) >> 5;
    int lane = threadIdx.x & 31;
    if (gw >= Nn) return;
    const float4* frow = (const float4*)&feat[gw * FIN];
    float4 x0 = frow[lane];
    float4 x1 = frow[lane + 32];
    uint2 r0, r1;
    *(__half2*)&r0.x = __floats2half2_rn(x0.x, x0.y);
    *(__half2*)&r0.y = __floats2half2_rn(x0.z, x0.w);
    *(__half2*)&r1.x = __floats2half2_rn(x1.x, x1.y);
    *(__half2*)&r1.y = __floats2half2_rn(x1.z, x1.w);
    ((uint2*)g_feat16)[gw * 64 + lane] = r0;
    ((uint2*)g_feat16)[gw * 64 + 32 + lane] = r1;

    int c0 = lane * 4, c1 = 128 + lane * 4;
    float s0 = 0.f, s1 = 0.f, d0 = 0.f, d1 = 0.f;
    #pragma unroll
    for (int j = 0; j < 4; j++) {
        float xa = (&x0.x)[j];
        float2 ws = ((const float2*)Wasrc)[c0 + j];
        float2 wd = ((const float2*)Wadst)[c0 + j];
        s0 += xa * ws.x; s1 += xa * ws.y;
        d0 += xa * wd.x; d1 += xa * wd.y;
        float xb = (&x1.x)[j];
        float2 ws1 = ((const float2*)Wasrc)[c1 + j];
        float2 wd1 = ((const float2*)Wadst)[c1 + j];
        s0 += xb * ws1.x; s1 += xb * ws1.y;
        d0 += xb * wd1.x; d1 += xb * wd1.y;
    }
    #pragma unroll
    for (int o = 16; o; o >>= 1) {
        s0 += __shfl_xor_sync(0xffffffffu, s0, o);
        s1 += __shfl_xor_sync(0xffffffffu, s1, o);
        d0 += __shfl_xor_sync(0xffffffffu, d0, o);
        d1 += __shfl_xor_sync(0xffffffffu, d1, o);
    }
    if (lane == 0) {
        ((float2*)g_asrc)[gw] = make_float2(s0, s1);
        ((float2*)g_adst)[gw] = make_float2(d0, d1);
    }
}

// ---------------- W fp32 -> fp16 (tiny) --------------------------------------
__global__ void wconv_kernel(const float* __restrict__ Wsrc,
                             const float* __restrict__ Wdst)
{
    int i = blockIdx.x * blockDim.x + threadIdx.x;
    if (i < FIN * HD / 2) {
        float2 a = ((const float2*)Wsrc)[i];
        float2 b = ((const float2*)Wdst)[i];
        *(__half2*)&g_w16[0][i * 2] = __floats2half2_rn(a.x, a.y);
        *(__half2*)&g_w16[1][i * 2] = __floats2half2_rn(b.x, b.y);
    }
}

// ---------------- tensor-core GEMM: Out = feat16 @ W16 -----------------------
__global__ __launch_bounds__(256) void gemm_tc_kernel()
{
    __shared__ __half Bs[FIN * 64];
    int wsel = blockIdx.y & 1;
    int nhalf = blockIdx.y >> 1;
    const uint2* wsrc = (const uint2*)g_w16[wsel];
    uint2* bs = (uint2*)Bs;
    for (int i = threadIdx.x; i < FIN * 16; i += 256) {
        int r = i >> 4, c = i & 15;
        bs[r * 16 + c] = wsrc[r * 32 + nhalf * 16 + c];
    }
    __syncthreads();
    int wid = threadIdx.x >> 5;
    int row0 = blockIdx.x * 128 + wid * 16;
    if (row0 >= Nn) return;

    wmma::fragment<wmma::accumulator, 16, 16, 16, float> acc[4];
    #pragma unroll
    for (int n = 0; n < 4; n++) wmma::fill_fragment(acc[n], 0.f);
    const __half* arow = g_feat16 + row0 * FIN;
    #pragma unroll 4
    for (int kt = 0; kt < 16; kt++) {
        wmma::fragment<wmma::matrix_a, 16, 16, 16, __half, wmma::row_major> af;
        wmma::load_matrix_sync(af, arow + kt * 16, FIN);
        #pragma unroll
        for (int n = 0; n < 4; n++) {
            wmma::fragment<wmma::matrix_b, 16, 16, 16, __half, wmma::row_major> bf;
            wmma::load_matrix_sync(bf, Bs + kt * 16 * 64 + n * 16, 64);
            wmma::mma_sync(acc[n], af, bf, acc[n]);
        }
    }
    float* Out = wsel ? g_hdst : g_hsrc;
    #pragma unroll
    for (int n = 0; n < 4; n++)
        wmma::store_matrix_sync(Out + row0 * HD + nhalf * 64 + n * 16,
                                acc[n], HD, wmma::mem_row_major);
}

// ---------------- init: zero counters + softmax sums -------------------------
__global__ void init_kernel() {
    int i = blockIdx.x * blockDim.x + threadIdx.x;
    if (i < Nn) {
        g_cnt[i] = 0;
        ((float2*)g_sumd)[i] = make_float2(0.f, 0.f);
        ((float2*)g_sums)[i] = make_float2(0.f, 0.f);
    }
}

// ---------------- CSR build --------------------------------------------------
__global__ void hist_kernel(const int* __restrict__ dst) {
    int i = blockIdx.x * blockDim.x + threadIdx.x;   // 4 edges per thread
    int e0 = i * 4;
    if (e0 + 3 < Ee) {
        int4 d = ((const int4*)dst)[i];
        atomicAdd(&g_cnt[d.x], 1);
        atomicAdd(&g_cnt[d.y], 1);
        atomicAdd(&g_cnt[d.z], 1);
        atomicAdd(&g_cnt[d.w], 1);
    } else {
        for (int e = e0; e < Ee; e++) atomicAdd(&g_cnt[dst[e]], 1);
    }
}

__global__ __launch_bounds__(1024) void scan_kernel() {
    __shared__ int part[1024];
    const int CH = (Nn + 1023) / 1024;
    int t = threadIdx.x;
    int start = t * CH;
    int s = 0;
    for (int i = 0; i < CH; i++) {
        int idx = start + i;
        if (idx < Nn) s += g_cnt[idx];
    }
    part[t] = s;
    __syncthreads();
    for (int off = 1; off < 1024; off <<= 1) {
        int v = (t >= off) ? part[t - off] : 0;
        __syncthreads();
        part[t] += v;
        __syncthreads();
    }
    int base = (t == 0) ? 0 : part[t - 1];
    for (int i = 0; i < CH; i++) {
        int idx = start + i;
        if (idx < Nn) {
            g_rp[idx] = base;
            g_cur[idx] = base;
            base += g_cnt[idx];
        }
    }
    if (t == 1023) g_rp[Nn] = Ee;
}

// ---------------- place + edge logits/exp + segment sums (fused) -------------
__global__ void place_edge_kernel(const int* __restrict__ src, const int* __restrict__ dst) {
    int e = blockIdx.x * blockDim.x + threadIdx.x;
    if (e >= Ee) return;
    int s = src[e], d = dst[e];
    int pos = atomicAdd(&g_cur[d], 1);
    g_srcc[pos] = s;
    float2 as = ((const float2*)g_asrc)[s];
    float2 ad = ((const float2*)g_adst)[d];
    float e0 = __expf(leaky(as.x + ad.x));
    float e1 = __expf(leaky(as.y + ad.y));
    ((float2*)g_acsr)[pos] = make_float2(e0, e1);
    atomicAdd(&g_sumd[d * 2], e0);     atomicAdd(&g_sumd[d * 2 + 1], e1);
    atomicAdd(&g_sums[s * 2], e0);     atomicAdd(&g_sums[s * 2 + 1], e1);
}

// ---------------- shared feat_trans epilogue helper --------------------------
__device__ __forceinline__ float4 feat_trans4(
    float4 acc, int lane, int k,
    const float* __restrict__ scale, const float* __restrict__ offset,
    const float* __restrict__ pemb)
{
    float s = acc.x + acc.y + acc.z + acc.w;
    float sq = acc.x * acc.x + acc.y * acc.y + acc.z * acc.z + acc.w * acc.w;
    #pragma unroll
    for (int o = 8; o; o >>= 1) {
        s  += __shfl_xor_sync(0xffffffffu, s,  o, 16);
        sq += __shfl_xor_sync(0xffffffffu, sq, o, 16);
    }
    float mean = s * (1.f / 64.f);
    float var = sq * (1.f / 64.f) - mean * mean + EPSf;
    float rs = rsqrtf(var);
    float4 sc = ((const float4*)scale)[k * 32 + lane];
    float4 of = ((const float4*)offset)[k * 32 + lane];
    float4 pe = ((const float4*)pemb)[k * 32 + lane];
    float4 y;
    y.x = (acc.x - mean) * sc.x * rs + of.x + pe.x;
    y.y = (acc.y - mean) * sc.y * rs + of.y + pe.y;
    y.z = (acc.z - mean) * sc.z * rs + of.z + pe.z;
    y.w = (acc.w - mean) * sc.w * rs + of.w + pe.w;
    return y;
}

__device__ __forceinline__ void store_half4(__half* __restrict__ out16,
                                            int idx4, float4 v)
{
    uint2 raw;
    *(__half2*)&raw.x = __floats2half2_rn(v.x, v.y);
    *(__half2*)&raw.y = __floats2half2_rn(v.z, v.w);
    ((uint2*)out16)[idx4] = raw;
}

// ---------------- ft0: feat_trans(h_src,0) -> h0t, plus fp16 copy of h_src ---
__global__ void ft0_kernel(const float* __restrict__ scale,
                           const float* __restrict__ offset,
                           const float* __restrict__ pemb)
{
    int gw = (blockIdx.x * blockDim.x + threadIdx.x) >> 5;
    int lane = threadIdx.x & 31;
    if (gw >= Nn) return;
    float4 x = ((const float4*)g_hsrc)[gw * 32 + lane];
    store_half4(g_h16[0], gw * 32 + lane, x);
    ((float4*)g_hs[2])[gw * 32 + lane] = feat_trans4(x, lane, 0, scale, offset, pemb);
}

// ---------------- fp16 gather core with warp register caching ----------------
// NORM=true (hop 1): lanes convert stored exp(logit) into the final symmetric
// softmax weight in-place (needs sd = sumd[node], scattered sums[src]).
template<bool NORM>
__device__ __forceinline__ float4 gather_row(const __half* __restrict__ in16,
                                             int b, int e, int lane, int hh,
                                             float2 sd)
{
    const uint2* in = (const uint2*)in16;
    float4 acc = make_float4(0.f, 0.f, 0.f, 0.f);
    for (int base = b; base < e; base += 32) {
        int cnt = e - base;
        int sj = 0;
        float2 aj = make_float2(0.f, 0.f);
        if (base + lane < e) {
            sj = g_srcc[base + lane];
            aj = ((const float2*)g_acsr)[base + lane];
            if (NORM) {
                float2 ss = ((const float2*)g_sums)[sj];
                aj.x = sqrtf(fmaxf(aj.x / sd.x, EPSf) * fmaxf(aj.x / ss.x, EPSf));
                aj.y = sqrtf(fmaxf(aj.y / sd.y, EPSf) * fmaxf(aj.y / ss.y, EPSf));
                ((float2*)g_acsr)[base + lane] = aj;
            }
        }
        if (cnt >= 32) {
            #pragma unroll 8
            for (int j = 0; j < 32; j++) {
                int s = __shfl_sync(0xffffffffu, sj, j);
                float a0 = __shfl_sync(0xffffffffu, aj.x, j);
                float a1 = __shfl_sync(0xffffffffu, aj.y, j);
                float a = hh ? a1 : a0;
                uint2 raw = in[s * 32 + lane];
                float2 lo = __half22float2(*(const __half2*)&raw.x);
                float2 hi = __half22float2(*(const __half2*)&raw.y);
                acc.x += a * lo.x; acc.y += a * lo.y;
                acc.z += a * hi.x; acc.w += a * hi.y;
            }
        } else {
            for (int j = 0; j < cnt; j++) {
                int s = __shfl_sync(0xffffffffu, sj, j);
                float a0 = __shfl_sync(0xffffffffu, aj.x, j);
                float a1 = __shfl_sync(0xffffffffu, aj.y, j);
                float a = hh ? a1 : a0;
                uint2 raw = in[s * 32 + lane];
                float2 lo = __half22float2(*(const __half2*)&raw.x);
                float2 hi = __half22float2(*(const __half2*)&raw.y);
                acc.x += a * lo.x; acc.y += a * lo.y;
                acc.z += a * hi.x; acc.w += a * hi.y;
            }
        }
    }
    return acc;
}

// ---------------- hop 1: normalize weights + gather + feat_trans -------------
__global__ __launch_bounds__(256) void hop1_kernel(
    const float* __restrict__ scale, const float* __restrict__ offset,
    const float* __restrict__ pemb)
{
    int gw = (blockIdx.x * blockDim.x + threadIdx.x) >> 5;
    int lane = threadIdx.x & 31;
    if (gw >= Nn) return;
    int hh = lane >> 4;
    int b = g_rp[gw], e = g_rp[gw + 1];
    float2 sd = ((const float2*)g_sumd)[gw];
    float4 acc = gather_row<true>(g_h16[0], b, e, lane, hh, sd);
    store_half4(g_h16[1], gw * 32 + lane, acc);
    ((float4*)g_hs[0])[gw * 32 + lane] =
        feat_trans4(acc, lane, 1, scale, offset, pemb);
}

// ---------------- hop 2: gather + feat_trans ---------------------------------
__global__ __launch_bounds__(256) void hop2_kernel(
    const float* __restrict__ scale, const float* __restrict__ offset,
    const float* __restrict__ pemb)
{
    int gw = (blockIdx.x * blockDim.x + threadIdx.x) >> 5;
    int lane = threadIdx.x & 31;
    if (gw >= Nn) return;
    int hh = lane >> 4;
    int b = g_rp[gw], e = g_rp[gw + 1];
    float4 acc = gather_row<false>(g_h16[1], b, e, lane, hh,
                                   make_float2(1.f, 1.f));
    store_half4(g_h16[2], gw * 32 + lane, acc);
    ((float4*)g_hs[1])[gw * 32 + lane] =
        feat_trans4(acc, lane, 2, scale, offset, pemb);
}

// ---------------- hop 3 + feat_trans + hop attention + residual + bias -------
__global__ __launch_bounds__(256) void hop3_final_kernel(
    const float* __restrict__ scale, const float* __restrict__ offset,
    const float* __restrict__ pemb,
    const float* __restrict__ attn_l, const float* __restrict__ attn_r,
    const float* __restrict__ bias,
    float* __restrict__ out)
{
    int gw = (blockIdx.x * blockDim.x + threadIdx.x) >> 5;
    int lane = threadIdx.x & 31;
    if (gw >= Nn) return;
    int hh = lane >> 4;
    int b = g_rp[gw], e = g_rp[gw + 1];
    float4 acc = gather_row<false>(g_h16[2], b, e, lane, hh,
                                   make_float2(1.f, 1.f));
    float4 s2 = feat_trans4(acc, lane, 3, scale, offset, pemb);

    float4 s0 = ((const float4*)g_hs[0])[gw * 32 + lane];
    float4 s1 = ((const float4*)g_hs[1])[gw * 32 + lane];
    float4 h0 = ((const float4*)g_hs[2])[gw * 32 + lane];
    float4 al4 = ((const float4*)attn_l)[lane];
    float4 ar4 = ((const float4*)attn_r)[lane];

    float al = h0.x * al4.x + h0.y * al4.y + h0.z * al4.z + h0.w * al4.w;
    float w0 = s0.x * ar4.x + s0.y * ar4.y + s0.z * ar4.z + s0.w * ar4.w;
    float w1 = s1.x * ar4.x + s1.y * ar4.y + s1.z * ar4.z + s1.w * ar4.w;
    float w2 = s2.x * ar4.x + s2.y * ar4.y + s2.z * ar4.z + s2.w * ar4.w;
    #pragma unroll
    for (int o = 8; o; o >>= 1) {
        al += __shfl_xor_sync(0xffffffffu, al, o, 16);
        w0 += __shfl_xor_sync(0xffffffffu, w0, o, 16);
        w1 += __shfl_xor_sync(0xffffffffu, w1, o, 16);
        w2 += __shfl_xor_sync(0xffffffffu, w2, o, 16);
    }
    float l0 = leaky(w0 + al), l1 = leaky(w1 + al), l2 = leaky(w2 + al);
    float m = fmaxf(l0, fmaxf(l1, l2));
    float e0 = __expf(l0 - m), e1 = __expf(l1 - m), e2 = __expf(l2 - m);
    float inv = 1.f / (e0 + e1 + e2);
    e0 *= inv; e1 *= inv; e2 *= inv;

    float4 hd = ((const float4*)g_hdst)[gw * 32 + lane];
    float4 b4 = ((const float4*)bias)[lane];
    float4 o4;
    o4.x = s0.x * e0 + s1.x * e1 + s2.x * e2 + hd.x + b4.x;
    o4.y = s0.y * e0 + s1.y * e1 + s2.y * e2 + hd.y + b4.y;
    o4.z = s0.z * e0 + s1.z * e1 + s2.z * e2 + hd.z + b4.z;
    o4.w = s0.w * e0 + s1.w * e1 + s2.w * e2 + hd.w + b4.w;
    ((float4*)out)[gw * 32 + lane] = o4;
}

// ---------------- launch ------------------------------------------------------
extern "C" void kernel_launch(void* const* d_in, const int* in_sizes, int n_in,
                              void* d_out, int out_size)
{
    const float* feat  = (const float*)d_in[0];
    const int*   src   = (const int*)d_in[1];
    const int*   dst   = (const int*)d_in[2];
    const float* Wsrc  = (const float*)d_in[3];
    const float* Wdst  = (const float*)d_in[4];
    const float* bdst  = (const float*)d_in[5];
    const float* Wasrc = (const float*)d_in[6];
    const float* Wadst = (const float*)d_in[7];
    const float* scale = (const float*)d_in[8];
    const float* offs  = (const float*)d_in[9];
    const float* pemb  = (const float*)d_in[10];
    const float* hal   = (const float*)d_in[11];
    const float* har   = (const float*)d_in[12];
    float* out = (float*)d_out;

    const int EG = (Ee + 255) / 256;
    const int NWG = (Nn * 32 + 255) / 256;

    // fp16 conversion + attention projections (one pass over feat)
    convert_attn_kernel<<<NWG, 256>>>(feat, Wasrc, Wadst);
    wconv_kernel<<<(FIN * HD / 2 + 255) / 256, 256>>>(Wsrc, Wdst);

    // tensor-core projections
    gemm_tc_kernel<<<dim3((Nn + 127) / 128, 4), 256>>>();

    // CSR build + fused edge logits/exp/sums
    init_kernel<<<(Nn + 255) / 256, 256>>>();
    hist_kernel<<<(Ee / 4 + 255) / 256, 256>>>(dst);
    scan_kernel<<<1, 1024>>>();
    place_edge_kernel<<<EG, 256>>>(src, dst);

    // h0 = feat_trans(h_src, 0) + fp16 copy of h_src
    ft0_kernel<<<NWG, 256>>>(scale, offs, pemb);

    // diffusion hops (hop1 normalizes edge weights in-place)
    hop1_kernel<<<NWG, 256>>>(scale, offs, pemb);
    hop2_kernel<<<NWG, 256>>>(scale, offs, pemb);
    hop3_final_kernel<<<NWG, 256>>>(scale, offs, pemb, hal, har, bdst, out);
}

// round 12
// speedup vs baseline: 1.9959x; 1.0347x over previous
#include <cuda_runtime.h>
#include <cuda_fp16.h>
#include <mma.h>

using namespace nvcuda;

#define Nn 50000
#define Ee 1600000
#define FIN 256
#define HD 128
#define NEG 0.2f
#define EPSf 1e-9f

// ---------------- scratch (static device globals) ----------------------------
__device__ float  g_hsrc[Nn * HD];        // fp32 h_src
__device__ float  g_hdst[Nn * HD];        // residual branch (bias added at end)
__device__ __half g_feat16[Nn * FIN];     // fp16 feat for TC GEMM
__device__ __half g_w16[2][FIN * HD];     // fp16 W_src / W_dst
__device__ __half g_h16[3][Nn * HD];      // fp16 gather sources
__device__ __half g_hs16[3][Nn * HD];     // fp16 transformed hops: [0]=hs1,[1]=hs2,[2]=h0
__device__ float  g_asrc[Nn * 2];
__device__ float  g_adst[Nn * 2];
__device__ float  g_acsr[Ee * 2];         // CSR: exp(logit) then (after hop1) weight
__device__ int    g_srcc[Ee];
__device__ int    g_cnt[Nn];
__device__ int    g_rp[Nn + 1];
__device__ int    g_cur[Nn];
__device__ float  g_sums[Nn * 2];         // src-direction softmax denominators

__device__ __forceinline__ float leaky(float x) { return x > 0.f ? x : NEG * x; }

// ---------------- fused: feat fp32->fp16 + attention projections -------------
__global__ void convert_attn_kernel(const float* __restrict__ feat,
                                    const float* __restrict__ Wasrc,
                                    const float* __restrict__ Wadst)
{
    int gw = (blockIdx.x * blockDim.x + threadIdx.x) >> 5;
    int lane = threadIdx.x & 31;
    if (gw >= Nn) return;
    const float4* frow = (const float4*)&feat[gw * FIN];
    float4 x0 = frow[lane];
    float4 x1 = frow[lane + 32];
    uint2 r0, r1;
    *(__half2*)&r0.x = __floats2half2_rn(x0.x, x0.y);
    *(__half2*)&r0.y = __floats2half2_rn(x0.z, x0.w);
    *(__half2*)&r1.x = __floats2half2_rn(x1.x, x1.y);
    *(__half2*)&r1.y = __floats2half2_rn(x1.z, x1.w);
    ((uint2*)g_feat16)[gw * 64 + lane] = r0;
    ((uint2*)g_feat16)[gw * 64 + 32 + lane] = r1;

    int c0 = lane * 4, c1 = 128 + lane * 4;
    float s0 = 0.f, s1 = 0.f, d0 = 0.f, d1 = 0.f;
    #pragma unroll
    for (int j = 0; j < 4; j++) {
        float xa = (&x0.x)[j];
        float2 ws = ((const float2*)Wasrc)[c0 + j];
        float2 wd = ((const float2*)Wadst)[c0 + j];
        s0 += xa * ws.x; s1 += xa * ws.y;
        d0 += xa * wd.x; d1 += xa * wd.y;
        float xb = (&x1.x)[j];
        float2 ws1 = ((const float2*)Wasrc)[c1 + j];
        float2 wd1 = ((const float2*)Wadst)[c1 + j];
        s0 += xb * ws1.x; s1 += xb * ws1.y;
        d0 += xb * wd1.x; d1 += xb * wd1.y;
    }
    #pragma unroll
    for (int o = 16; o; o >>= 1) {
        s0 += __shfl_xor_sync(0xffffffffu, s0, o);
        s1 += __shfl_xor_sync(0xffffffffu, s1, o);
        d0 += __shfl_xor_sync(0xffffffffu, d0, o);
        d1 += __shfl_xor_sync(0xffffffffu, d1, o);
    }
    if (lane == 0) {
        ((float2*)g_asrc)[gw] = make_float2(s0, s1);
        ((float2*)g_adst)[gw] = make_float2(d0, d1);
    }
}

// ---------------- W fp32 -> fp16 (tiny) --------------------------------------
__global__ void wconv_kernel(const float* __restrict__ Wsrc,
                             const float* __restrict__ Wdst)
{
    int i = blockIdx.x * blockDim.x + threadIdx.x;
    if (i < FIN * HD / 2) {
        float2 a = ((const float2*)Wsrc)[i];
        float2 b = ((const float2*)Wdst)[i];
        *(__half2*)&g_w16[0][i * 2] = __floats2half2_rn(a.x, a.y);
        *(__half2*)&g_w16[1][i * 2] = __floats2half2_rn(b.x, b.y);
    }
}

// ---------------- tensor-core GEMM: Out = feat16 @ W16 -----------------------
__global__ __launch_bounds__(256) void gemm_tc_kernel()
{
    __shared__ __half Bs[FIN * 64];
    int wsel = blockIdx.y & 1;
    int nhalf = blockIdx.y >> 1;
    const uint2* wsrc = (const uint2*)g_w16[wsel];
    uint2* bs = (uint2*)Bs;
    for (int i = threadIdx.x; i < FIN * 16; i += 256) {
        int r = i >> 4, c = i & 15;
        bs[r * 16 + c] = wsrc[r * 32 + nhalf * 16 + c];
    }
    __syncthreads();
    int wid = threadIdx.x >> 5;
    int row0 = blockIdx.x * 128 + wid * 16;
    if (row0 >= Nn) return;

    wmma::fragment<wmma::accumulator, 16, 16, 16, float> acc[4];
    #pragma unroll
    for (int n = 0; n < 4; n++) wmma::fill_fragment(acc[n], 0.f);
    const __half* arow = g_feat16 + row0 * FIN;
    #pragma unroll 4
    for (int kt = 0; kt < 16; kt++) {
        wmma::fragment<wmma::matrix_a, 16, 16, 16, __half, wmma::row_major> af;
        wmma::load_matrix_sync(af, arow + kt * 16, FIN);
        #pragma unroll
        for (int n = 0; n < 4; n++) {
            wmma::fragment<wmma::matrix_b, 16, 16, 16, __half, wmma::row_major> bf;
            wmma::load_matrix_sync(bf, Bs + kt * 16 * 64 + n * 16, 64);
            wmma::mma_sync(acc[n], af, bf, acc[n]);
        }
    }
    float* Out = wsel ? g_hdst : g_hsrc;
    #pragma unroll
    for (int n = 0; n < 4; n++)
        wmma::store_matrix_sync(Out + row0 * HD + nhalf * 64 + n * 16,
                                acc[n], HD, wmma::mem_row_major);
}

// ---------------- init: zero counters + src softmax sums ---------------------
__global__ void init_kernel() {
    int i = blockIdx.x * blockDim.x + threadIdx.x;
    if (i < Nn) {
        g_cnt[i] = 0;
        ((float2*)g_sums)[i] = make_float2(0.f, 0.f);
    }
}

// ---------------- CSR build --------------------------------------------------
__global__ void hist_kernel(const int* __restrict__ dst) {
    int i = blockIdx.x * blockDim.x + threadIdx.x;   // 4 edges per thread
    int e0 = i * 4;
    if (e0 + 3 < Ee) {
        int4 d = ((const int4*)dst)[i];
        atomicAdd(&g_cnt[d.x], 1);
        atomicAdd(&g_cnt[d.y], 1);
        atomicAdd(&g_cnt[d.z], 1);
        atomicAdd(&g_cnt[d.w], 1);
    } else {
        for (int e = e0; e < Ee; e++) atomicAdd(&g_cnt[dst[e]], 1);
    }
}

__global__ __launch_bounds__(1024) void scan_kernel() {
    __shared__ int part[1024];
    const int CH = (Nn + 1023) / 1024;
    int t = threadIdx.x;
    int start = t * CH;
    int s = 0;
    for (int i = 0; i < CH; i++) {
        int idx = start + i;
        if (idx < Nn) s += g_cnt[idx];
    }
    part[t] = s;
    __syncthreads();
    for (int off = 1; off < 1024; off <<= 1) {
        int v = (t >= off) ? part[t - off] : 0;
        __syncthreads();
        part[t] += v;
        __syncthreads();
    }
    int base = (t == 0) ? 0 : part[t - 1];
    for (int i = 0; i < CH; i++) {
        int idx = start + i;
        if (idx < Nn) {
            g_rp[idx] = base;
            g_cur[idx] = base;
            base += g_cnt[idx];
        }
    }
    if (t == 1023) g_rp[Nn] = Ee;
}

// ---------------- place + edge logits/exp + src-sum atomics ------------------
__global__ void place_edge_kernel(const int* __restrict__ src, const int* __restrict__ dst) {
    int e = blockIdx.x * blockDim.x + threadIdx.x;
    if (e >= Ee) return;
    int s = src[e], d = dst[e];
    int pos = atomicAdd(&g_cur[d], 1);
    g_srcc[pos] = s;
    float2 as = ((const float2*)g_asrc)[s];
    float2 ad = ((const float2*)g_adst)[d];
    float e0 = __expf(leaky(as.x + ad.x));
    float e1 = __expf(leaky(as.y + ad.y));
    ((float2*)g_acsr)[pos] = make_float2(e0, e1);
    atomicAdd(&g_sums[s * 2], e0);     atomicAdd(&g_sums[s * 2 + 1], e1);
}

// ---------------- shared feat_trans epilogue helper --------------------------
__device__ __forceinline__ float4 feat_trans4(
    float4 acc, int lane, int k,
    const float* __restrict__ scale, const float* __restrict__ offset,
    const float* __restrict__ pemb)
{
    float s = acc.x + acc.y + acc.z + acc.w;
    float sq = acc.x * acc.x + acc.y * acc.y + acc.z * acc.z + acc.w * acc.w;
    #pragma unroll
    for (int o = 8; o; o >>= 1) {
        s  += __shfl_xor_sync(0xffffffffu, s,  o, 16);
        sq += __shfl_xor_sync(0xffffffffu, sq, o, 16);
    }
    float mean = s * (1.f / 64.f);
    float var = sq * (1.f / 64.f) - mean * mean + EPSf;
    float rs = rsqrtf(var);
    float4 sc = ((const float4*)scale)[k * 32 + lane];
    float4 of = ((const float4*)offset)[k * 32 + lane];
    float4 pe = ((const float4*)pemb)[k * 32 + lane];
    float4 y;
    y.x = (acc.x - mean) * sc.x * rs + of.x + pe.x;
    y.y = (acc.y - mean) * sc.y * rs + of.y + pe.y;
    y.z = (acc.z - mean) * sc.z * rs + of.z + pe.z;
    y.w = (acc.w - mean) * sc.w * rs + of.w + pe.w;
    return y;
}

__device__ __forceinline__ void store_half4(__half* __restrict__ out16,
                                            int idx4, float4 v)
{
    uint2 raw;
    *(__half2*)&raw.x = __floats2half2_rn(v.x, v.y);
    *(__half2*)&raw.y = __floats2half2_rn(v.z, v.w);
    ((uint2*)out16)[idx4] = raw;
}

__device__ __forceinline__ float4 load_half4(const __half* __restrict__ in16,
                                             int idx4)
{
    uint2 raw = ((const uint2*)in16)[idx4];
    float2 lo = __half22float2(*(const __half2*)&raw.x);
    float2 hi = __half22float2(*(const __half2*)&raw.y);
    return make_float4(lo.x, lo.y, hi.x, hi.y);
}

// ---------------- ft0: feat_trans(h_src,0) -> h0 (fp16), + fp16 h_src --------
__global__ void ft0_kernel(const float* __restrict__ scale,
                           const float* __restrict__ offset,
                           const float* __restrict__ pemb)
{
    int gw = (blockIdx.x * blockDim.x + threadIdx.x) >> 5;
    int lane = threadIdx.x & 31;
    if (gw >= Nn) return;
    float4 x = ((const float4*)g_hsrc)[gw * 32 + lane];
    store_half4(g_h16[0], gw * 32 + lane, x);
    store_half4(g_hs16[2], gw * 32 + lane,
                feat_trans4(x, lane, 0, scale, offset, pemb));
}

// ---------------- fp16 gather core with warp register caching ----------------
template<bool NORM>
__device__ __forceinline__ float4 gather_row(const __half* __restrict__ in16,
                                             int b, int e, int lane, int hh,
                                             float2 sd)
{
    const uint2* in = (const uint2*)in16;
    float4 acc = make_float4(0.f, 0.f, 0.f, 0.f);
    for (int base = b; base < e; base += 32) {
        int cnt = e - base;
        int sj = 0;
        float2 aj = make_float2(0.f, 0.f);
        if (base + lane < e) {
            sj = g_srcc[base + lane];
            aj = ((const float2*)g_acsr)[base + lane];
            if (NORM) {
                float2 ss = ((const float2*)g_sums)[sj];
                aj.x = sqrtf(fmaxf(aj.x / sd.x, EPSf) * fmaxf(aj.x / ss.x, EPSf));
                aj.y = sqrtf(fmaxf(aj.y / sd.y, EPSf) * fmaxf(aj.y / ss.y, EPSf));
                ((float2*)g_acsr)[base + lane] = aj;
            }
        }
        if (cnt >= 32) {
            #pragma unroll 8
            for (int j = 0; j < 32; j++) {
                int s = __shfl_sync(0xffffffffu, sj, j);
                float a0 = __shfl_sync(0xffffffffu, aj.x, j);
                float a1 = __shfl_sync(0xffffffffu, aj.y, j);
                float a = hh ? a1 : a0;
                uint2 raw = in[s * 32 + lane];
                float2 lo = __half22float2(*(const __half2*)&raw.x);
                float2 hi = __half22float2(*(const __half2*)&raw.y);
                acc.x += a * lo.x; acc.y += a * lo.y;
                acc.z += a * hi.x; acc.w += a * hi.y;
            }
        } else {
            for (int j = 0; j < cnt; j++) {
                int s = __shfl_sync(0xffffffffu, sj, j);
                float a0 = __shfl_sync(0xffffffffu, aj.x, j);
                float a1 = __shfl_sync(0xffffffffu, aj.y, j);
                float a = hh ? a1 : a0;
                uint2 raw = in[s * 32 + lane];
                float2 lo = __half22float2(*(const __half2*)&raw.x);
                float2 hi = __half22float2(*(const __half2*)&raw.y);
                acc.x += a * lo.x; acc.y += a * lo.y;
                acc.z += a * hi.x; acc.w += a * hi.y;
            }
        }
    }
    return acc;
}

// ---------------- hop 1: in-warp dst-sum + normalize + gather + feat_trans ---
__global__ __launch_bounds__(256) void hop1_kernel(
    const float* __restrict__ scale, const float* __restrict__ offset,
    const float* __restrict__ pemb)
{
    int gw = (blockIdx.x * blockDim.x + threadIdx.x) >> 5;
    int lane = threadIdx.x & 31;
    if (gw >= Nn) return;
    int hh = lane >> 4;
    int b = g_rp[gw], e = g_rp[gw + 1];

    // dst-direction denominator: coalesced pre-pass + full warp reduction
    float2 sd = make_float2(0.f, 0.f);
    for (int pos = b + lane; pos < e; pos += 32) {
        float2 ex = ((const float2*)g_acsr)[pos];
        sd.x += ex.x; sd.y += ex.y;
    }
    #pragma unroll
    for (int o = 16; o; o >>= 1) {
        sd.x += __shfl_xor_sync(0xffffffffu, sd.x, o);
        sd.y += __shfl_xor_sync(0xffffffffu, sd.y, o);
    }

    float4 acc = gather_row<true>(g_h16[0], b, e, lane, hh, sd);
    store_half4(g_h16[1], gw * 32 + lane, acc);
    store_half4(g_hs16[0], gw * 32 + lane,
                feat_trans4(acc, lane, 1, scale, offset, pemb));
}

// ---------------- hop 2: gather + feat_trans ---------------------------------
__global__ __launch_bounds__(256) void hop2_kernel(
    const float* __restrict__ scale, const float* __restrict__ offset,
    const float* __restrict__ pemb)
{
    int gw = (blockIdx.x * blockDim.x + threadIdx.x) >> 5;
    int lane = threadIdx.x & 31;
    if (gw >= Nn) return;
    int hh = lane >> 4;
    int b = g_rp[gw], e = g_rp[gw + 1];
    float4 acc = gather_row<false>(g_h16[1], b, e, lane, hh,
                                   make_float2(1.f, 1.f));
    store_half4(g_h16[2], gw * 32 + lane, acc);
    store_half4(g_hs16[1], gw * 32 + lane,
                feat_trans4(acc, lane, 2, scale, offset, pemb));
}

// ---------------- hop 3 + feat_trans + hop attention + residual + bias -------
__global__ __launch_bounds__(256) void hop3_final_kernel(
    const float* __restrict__ scale, const float* __restrict__ offset,
    const float* __restrict__ pemb,
    const float* __restrict__ attn_l, const float* __restrict__ attn_r,
    const float* __restrict__ bias,
    float* __restrict__ out)
{
    int gw = (blockIdx.x * blockDim.x + threadIdx.x) >> 5;
    int lane = threadIdx.x & 31;
    if (gw >= Nn) return;
    int hh = lane >> 4;
    int b = g_rp[gw], e = g_rp[gw + 1];
    float4 acc = gather_row<false>(g_h16[2], b, e, lane, hh,
                                   make_float2(1.f, 1.f));
    float4 s2 = feat_trans4(acc, lane, 3, scale, offset, pemb);

    float4 s0 = load_half4(g_hs16[0], gw * 32 + lane);
    float4 s1 = load_half4(g_hs16[1], gw * 32 + lane);
    float4 h0 = load_half4(g_hs16[2], gw * 32 + lane);
    float4 al4 = ((const float4*)attn_l)[lane];
    float4 ar4 = ((const float4*)attn_r)[lane];

    float al = h0.x * al4.x + h0.y * al4.y + h0.z * al4.z + h0.w * al4.w;
    float w0 = s0.x * ar4.x + s0.y * ar4.y + s0.z * ar4.z + s0.w * ar4.w;
    float w1 = s1.x * ar4.x + s1.y * ar4.y + s1.z * ar4.z + s1.w * ar4.w;
    float w2 = s2.x * ar4.x + s2.y * ar4.y + s2.z * ar4.z + s2.w * ar4.w;
    #pragma unroll
    for (int o = 8; o; o >>= 1) {
        al += __shfl_xor_sync(0xffffffffu, al, o, 16);
        w0 += __shfl_xor_sync(0xffffffffu, w0, o, 16);
        w1 += __shfl_xor_sync(0xffffffffu, w1, o, 16);
        w2 += __shfl_xor_sync(0xffffffffu, w2, o, 16);
    }
    float l0 = leaky(w0 + al), l1 = leaky(w1 + al), l2 = leaky(w2 + al);
    float m = fmaxf(l0, fmaxf(l1, l2));
    float e0 = __expf(l0 - m), e1 = __expf(l1 - m), e2 = __expf(l2 - m);
    float inv = 1.f / (e0 + e1 + e2);
    e0 *= inv; e1 *= inv; e2 *= inv;

    float4 hd = ((const float4*)g_hdst)[gw * 32 + lane];
    float4 b4 = ((const float4*)bias)[lane];
    float4 o4;
    o4.x = s0.x * e0 + s1.x * e1 + s2.x * e2 + hd.x + b4.x;
    o4.y = s0.y * e0 + s1.y * e1 + s2.y * e2 + hd.y + b4.y;
    o4.z = s0.z * e0 + s1.z * e1 + s2.z * e2 + hd.z + b4.z;
    o4.w = s0.w * e0 + s1.w * e1 + s2.w * e2 + hd.w + b4.w;
    ((float4*)out)[gw * 32 + lane] = o4;
}

// ---------------- launch ------------------------------------------------------
extern "C" void kernel_launch(void* const* d_in, const int* in_sizes, int n_in,
                              void* d_out, int out_size)
{
    const float* feat  = (const float*)d_in[0];
    const int*   src   = (const int*)d_in[1];
    const int*   dst   = (const int*)d_in[2];
    const float* Wsrc  = (const float*)d_in[3];
    const float* Wdst  = (const float*)d_in[4];
    const float* bdst  = (const float*)d_in[5];
    const float* Wasrc = (const float*)d_in[6];
    const float* Wadst = (const float*)d_in[7];
    const float* scale = (const float*)d_in[8];
    const float* offs  = (const float*)d_in[9];
    const float* pemb  = (const float*)d_in[10];
    const float* hal   = (const float*)d_in[11];
    const float* har   = (const float*)d_in[12];
    float* out = (float*)d_out;

    const int EG = (Ee + 255) / 256;
    const int NWG = (Nn * 32 + 255) / 256;

    // fp16 conversion + attention projections (one pass over feat)
    convert_attn_kernel<<<NWG, 256>>>(feat, Wasrc, Wadst);
    wconv_kernel<<<(FIN * HD / 2 + 255) / 256, 256>>>(Wsrc, Wdst);

    // tensor-core projections
    gemm_tc_kernel<<<dim3((Nn + 127) / 128, 4), 256>>>();

    // CSR build + fused edge logits/exp/src-sums
    init_kernel<<<(Nn + 255) / 256, 256>>>();
    hist_kernel<<<(Ee / 4 + 255) / 256, 256>>>(dst);
    scan_kernel<<<1, 1024>>>();
    place_edge_kernel<<<EG, 256>>>(src, dst);

    // h0 = feat_trans(h_src, 0) + fp16 copy of h_src
    ft0_kernel<<<NWG, 256>>>(scale, offs, pemb);

    // diffusion hops (hop1 computes dst-sums in-warp and normalizes in-place)
    hop1_kernel<<<NWG, 256>>>(scale, offs, pemb);
    hop2_kernel<<<NWG, 256>>>(scale, offs, pemb);
    hop3_final_kernel<<<NWG, 256>>>(scale, offs, pemb, hal, har, bdst, out);
}